// round 6
// baseline (speedup 1.0000x reference)
#include <cuda_runtime.h>
#include <cstdint>

#define DIM 128
#define NMAX 100000
#define EMAX 1600000
#define SCAN_BLK 1024
#define GW 8    // warps per block in fused kernel
#define MB 8    // nodes per warp-batch in fused kernel

// Scratch (device globals: allocation-free per harness rules)
__device__ float g_y[(size_t)NMAX * DIM];     // prescaled features h * inv_out
__device__ int   g_deg_out[NMAX];
__device__ int   g_deg_in[NMAX];
__device__ float g_inv_out[NMAX];
__device__ float g_inv_in[NMAX];
__device__ int   g_row_ptr[NMAX + 1];
__device__ int   g_cursor[NMAX];
__device__ int   g_csr_src[EMAX];
__device__ int   g_blksum[256];
__device__ int   g_blkoff[256];
__device__ int   g_scan_tmp[NMAX];
__device__ float g_hsum[DIM];

// ---------------------------------------------------------------------------
// 1) degree counting, vectorized 4 edges/thread
// ---------------------------------------------------------------------------
__global__ void deg_kernel(const int4* __restrict__ src4, const int4* __restrict__ dst4,
                           const int* __restrict__ src, const int* __restrict__ dst,
                           int n4, int n_edges) {
    int i = blockIdx.x * blockDim.x + threadIdx.x;
    if (i < n4) {
        int4 s = src4[i];
        atomicAdd(&g_deg_out[s.x], 1); atomicAdd(&g_deg_out[s.y], 1);
        atomicAdd(&g_deg_out[s.z], 1); atomicAdd(&g_deg_out[s.w], 1);
        int4 d = dst4[i];
        atomicAdd(&g_deg_in[d.x], 1); atomicAdd(&g_deg_in[d.y], 1);
        atomicAdd(&g_deg_in[d.z], 1); atomicAdd(&g_deg_in[d.w], 1);
    }
    if (blockIdx.x == gridDim.x - 1 && threadIdx.x == blockDim.x - 1) {
        for (int e = n4 * 4; e < n_edges; e++) {
            atomicAdd(&g_deg_out[src[e]], 1);
            atomicAdd(&g_deg_in[dst[e]], 1);
        }
    }
}

// ---------------------------------------------------------------------------
// 2) exclusive scan of deg_in -> row_ptr (2-level scan); norms in scan3
// ---------------------------------------------------------------------------
__global__ void scan1_kernel(int n) {
    __shared__ int sm[SCAN_BLK];
    int i = blockIdx.x * SCAN_BLK + threadIdx.x;
    int v = (i < n) ? g_deg_in[i] : 0;
    sm[threadIdx.x] = v;
    __syncthreads();
#pragma unroll
    for (int off = 1; off < SCAN_BLK; off <<= 1) {
        int t = (threadIdx.x >= off) ? sm[threadIdx.x - off] : 0;
        __syncthreads();
        sm[threadIdx.x] += t;
        __syncthreads();
    }
    if (i < n) g_scan_tmp[i] = sm[threadIdx.x] - v;   // exclusive
    if (threadIdx.x == SCAN_BLK - 1) g_blksum[blockIdx.x] = sm[SCAN_BLK - 1];
}

__global__ void scan2_kernel(int nb) {
    __shared__ int sm[256];
    int t = threadIdx.x;
    int v = (t < nb) ? g_blksum[t] : 0;
    sm[t] = v;
    __syncthreads();
#pragma unroll
    for (int off = 1; off < 256; off <<= 1) {
        int u = (t >= off) ? sm[t - off] : 0;
        __syncthreads();
        sm[t] += u;
        __syncthreads();
    }
    if (t < nb) g_blkoff[t] = sm[t] - v;   // exclusive
}

__global__ void scan3_kernel(int n, int n_edges) {
    int i = blockIdx.x * blockDim.x + threadIdx.x;
    if (i < n) {
        int r = g_scan_tmp[i] + g_blkoff[i / SCAN_BLK];
        g_row_ptr[i] = r;
        g_cursor[i] = r;
        g_inv_out[i] = rsqrtf((float)(g_deg_out[i] + 1));
        g_inv_in[i]  = rsqrtf((float)(g_deg_in[i] + 1));
    }
    if (i == 0) g_row_ptr[n] = n_edges;
}

// ---------------------------------------------------------------------------
// 3) prescale features: y[n] = h[n] * inv_out[n]  (one float4 per thread)
// ---------------------------------------------------------------------------
__global__ void prescale_kernel(const float4* __restrict__ h4, int n4elems) {
    int i = blockIdx.x * blockDim.x + threadIdx.x;
    if (i < n4elems) {
        float sc = g_inv_out[i >> 5];
        float4 v = h4[i];
        ((float4*)g_y)[i] = make_float4(v.x * sc, v.y * sc, v.z * sc, v.w * sc);
    }
}

// ---------------------------------------------------------------------------
// 4) bucket fill: csr_src grouped by dst (4 edges/thread)
// ---------------------------------------------------------------------------
__global__ void fill_kernel(const int4* __restrict__ src4, const int4* __restrict__ dst4,
                            const int* __restrict__ src, const int* __restrict__ dst,
                            int n4, int n_edges) {
    int i = blockIdx.x * blockDim.x + threadIdx.x;
    if (i < n4) {
        int4 s = src4[i];
        int4 d = dst4[i];
        g_csr_src[atomicAdd(&g_cursor[d.x], 1)] = s.x;
        g_csr_src[atomicAdd(&g_cursor[d.y], 1)] = s.y;
        g_csr_src[atomicAdd(&g_cursor[d.z], 1)] = s.z;
        g_csr_src[atomicAdd(&g_cursor[d.w], 1)] = s.w;
    }
    if (blockIdx.x == gridDim.x - 1 && threadIdx.x == blockDim.x - 1) {
        for (int e = n4 * 4; e < n_edges; e++)
            g_csr_src[atomicAdd(&g_cursor[dst[e]], 1)] = src[e];
    }
}

// ---------------------------------------------------------------------------
// 5) FUSED: per warp-batch of MB dst rows:
//      a) x[d] = (y[d] + sum_s y[s]) * wi[d] -> smem   (single-level gather:
//         32 indices coalesced-loaded per lane, shfl-broadcast; y row loads
//         unrolled 8-way independent -> MLP 8)
//      b) GEMV y = relu(x @ W1 + b1), K-paired f32x2 accumulators,
//         node-sum into g_hsum.
// ---------------------------------------------------------------------------
__global__ __launch_bounds__(256, 2)
void fused_kernel(const float4* __restrict__ y4, const float* __restrict__ W1,
                  const float* __restrict__ b1, int n_nodes) {
    extern __shared__ float4 dyn[];
    float4* Wp   = dyn;          // [32][128] float4 = 64KB
    float4* xbuf = dyn + 4096;   // [GW][MB][32] float4 = 32KB

    for (int idx = threadIdx.x; idx < 4096; idx += blockDim.x) {
        int t2 = idx >> 7, j = idx & 127;
        Wp[idx] = make_float4(W1[(4 * t2 + 0) * 128 + j],
                              W1[(4 * t2 + 1) * 128 + j],
                              W1[(4 * t2 + 2) * 128 + j],
                              W1[(4 * t2 + 3) * 128 + j]);
    }
    __syncthreads();

    int lane = threadIdx.x & 31;
    int w    = threadIdx.x >> 5;
    int warp = blockIdx.x * GW + w;
    int nwarp = gridDim.x * GW;

    float bb[4], s[4];
#pragma unroll
    for (int c = 0; c < 4; c++) {
        bb[c] = b1[c * 32 + lane];
        s[c] = 0.f;
    }

    const ulonglong2* Wp2 = (const ulonglong2*)Wp;
    float4* xw = &xbuf[w * MB * 32];
    const ulonglong2* xb = (const ulonglong2*)xw;

    for (int base = warp * MB; base < n_nodes; base += nwarp * MB) {
        // ---- phase A: aggregate MB rows into xw ----
        for (int m = 0; m < MB; m++) {
            int d = base + m;
            float4 out = make_float4(0.f, 0.f, 0.f, 0.f);
            if (d < n_nodes) {
                float4 a0 = __ldg(&y4[(size_t)d * 32 + lane]);  // self loop
                float4 a1 = make_float4(0.f, 0.f, 0.f, 0.f);
                float4 a2 = make_float4(0.f, 0.f, 0.f, 0.f);
                float4 a3 = make_float4(0.f, 0.f, 0.f, 0.f);
                int beg = g_row_ptr[d], end = g_row_ptr[d + 1];
                for (int i0 = beg; i0 < end; i0 += 32) {
                    int cnt = min(32, end - i0);
                    int e = i0 + lane;
                    int idx = (e < end) ? g_csr_src[e] : 0;   // coalesced
                    int j = 0;
                    for (; j + 8 <= cnt; j += 8) {
                        int s0 = __shfl_sync(0xffffffffu, idx, j + 0);
                        int s1 = __shfl_sync(0xffffffffu, idx, j + 1);
                        int s2 = __shfl_sync(0xffffffffu, idx, j + 2);
                        int s3 = __shfl_sync(0xffffffffu, idx, j + 3);
                        int s4 = __shfl_sync(0xffffffffu, idx, j + 4);
                        int s5 = __shfl_sync(0xffffffffu, idx, j + 5);
                        int s6 = __shfl_sync(0xffffffffu, idx, j + 6);
                        int s7 = __shfl_sync(0xffffffffu, idx, j + 7);
                        float4 v0 = __ldg(&y4[(size_t)s0 * 32 + lane]);
                        float4 v1 = __ldg(&y4[(size_t)s1 * 32 + lane]);
                        float4 v2 = __ldg(&y4[(size_t)s2 * 32 + lane]);
                        float4 v3 = __ldg(&y4[(size_t)s3 * 32 + lane]);
                        float4 v4 = __ldg(&y4[(size_t)s4 * 32 + lane]);
                        float4 v5 = __ldg(&y4[(size_t)s5 * 32 + lane]);
                        float4 v6 = __ldg(&y4[(size_t)s6 * 32 + lane]);
                        float4 v7 = __ldg(&y4[(size_t)s7 * 32 + lane]);
                        a0.x += v0.x; a0.y += v0.y; a0.z += v0.z; a0.w += v0.w;
                        a1.x += v1.x; a1.y += v1.y; a1.z += v1.z; a1.w += v1.w;
                        a2.x += v2.x; a2.y += v2.y; a2.z += v2.z; a2.w += v2.w;
                        a3.x += v3.x; a3.y += v3.y; a3.z += v3.z; a3.w += v3.w;
                        a0.x += v4.x; a0.y += v4.y; a0.z += v4.z; a0.w += v4.w;
                        a1.x += v5.x; a1.y += v5.y; a1.z += v5.z; a1.w += v5.w;
                        a2.x += v6.x; a2.y += v6.y; a2.z += v6.z; a2.w += v6.w;
                        a3.x += v7.x; a3.y += v7.y; a3.z += v7.z; a3.w += v7.w;
                    }
                    if (j + 4 <= cnt) {
                        int s0 = __shfl_sync(0xffffffffu, idx, j + 0);
                        int s1 = __shfl_sync(0xffffffffu, idx, j + 1);
                        int s2 = __shfl_sync(0xffffffffu, idx, j + 2);
                        int s3 = __shfl_sync(0xffffffffu, idx, j + 3);
                        float4 v0 = __ldg(&y4[(size_t)s0 * 32 + lane]);
                        float4 v1 = __ldg(&y4[(size_t)s1 * 32 + lane]);
                        float4 v2 = __ldg(&y4[(size_t)s2 * 32 + lane]);
                        float4 v3 = __ldg(&y4[(size_t)s3 * 32 + lane]);
                        a0.x += v0.x; a0.y += v0.y; a0.z += v0.z; a0.w += v0.w;
                        a1.x += v1.x; a1.y += v1.y; a1.z += v1.z; a1.w += v1.w;
                        a2.x += v2.x; a2.y += v2.y; a2.z += v2.z; a2.w += v2.w;
                        a3.x += v3.x; a3.y += v3.y; a3.z += v3.z; a3.w += v3.w;
                        j += 4;
                    }
                    for (; j < cnt; j++) {
                        int s0 = __shfl_sync(0xffffffffu, idx, j);
                        float4 v0 = __ldg(&y4[(size_t)s0 * 32 + lane]);
                        a0.x += v0.x; a0.y += v0.y; a0.z += v0.z; a0.w += v0.w;
                    }
                }
                float wi = g_inv_in[d];
                out.x = (a0.x + a1.x + a2.x + a3.x) * wi;
                out.y = (a0.y + a1.y + a2.y + a3.y) * wi;
                out.z = (a0.z + a1.z + a2.z + a3.z) * wi;
                out.w = (a0.w + a1.w + a2.w + a3.w) * wi;
            }
            xw[m * 32 + lane] = out;
        }
        __syncwarp();

        // ---- phase B: GEMV over the MB staged rows ----
        unsigned long long acc[MB][4];
#pragma unroll
        for (int m = 0; m < MB; m++)
#pragma unroll
            for (int c = 0; c < 4; c++) acc[m][c] = 0ull;

#pragma unroll 2
        for (int t2 = 0; t2 < 32; t2++) {
            ulonglong2 wv[4];
#pragma unroll
            for (int c = 0; c < 4; c++)
                wv[c] = Wp2[t2 * 128 + c * 32 + lane];
#pragma unroll
            for (int m = 0; m < MB; m++) {
                ulonglong2 xm = xb[m * 32 + t2];   // broadcast
#pragma unroll
                for (int c = 0; c < 4; c++) {
                    asm("fma.rn.f32x2 %0, %1, %2, %0;"
                        : "+l"(acc[m][c]) : "l"(wv[c].x), "l"(xm.x));
                    asm("fma.rn.f32x2 %0, %1, %2, %0;"
                        : "+l"(acc[m][c]) : "l"(wv[c].y), "l"(xm.y));
                }
            }
        }

#pragma unroll
        for (int m = 0; m < MB; m++) {
            if (base + m >= n_nodes) break;
#pragma unroll
            for (int c = 0; c < 4; c++) {
                unsigned lo, hi;
                asm("mov.b64 {%0, %1}, %2;" : "=r"(lo), "=r"(hi) : "l"(acc[m][c]));
                float y = __uint_as_float(lo) + __uint_as_float(hi) + bb[c];
                s[c] += fmaxf(y, 0.f);
            }
        }
        __syncwarp();   // xbuf reuse safety
    }

#pragma unroll
    for (int c = 0; c < 4; c++)
        atomicAdd(&g_hsum[c * 32 + lane], s[c]);
}

// ---------------------------------------------------------------------------
// 6) classifier heads, split-K over 4 warps
// ---------------------------------------------------------------------------
__global__ void head_kernel(const float* __restrict__ Wc1, const float* __restrict__ bc1,
                            const float* __restrict__ Wc2, const float* __restrict__ bc2,
                            float* __restrict__ out, float inv_n) {
    __shared__ float red[128];
    int t = threadIdx.x;          // 0..127
    int o = t & 31;               // output index
    int part = t >> 5;            // k-quarter
    const float* Wc = (o < 16) ? Wc1 : Wc2;
    int c = o & 15;
    float acc = 0.f;
#pragma unroll 8
    for (int k = part * 32; k < part * 32 + 32; k++)
        acc += g_hsum[k] * Wc[k * 16 + c];
    red[t] = acc;
    __syncthreads();
    if (t < 32) {
        const float* bc = (t < 16) ? bc1 : bc2;
        float v = red[t] + red[t + 32] + red[t + 64] + red[t + 96];
        out[t] = v * inv_n + bc[c];
    }
}

// ---------------------------------------------------------------------------
extern "C" void kernel_launch(void* const* d_in, const int* in_sizes, int n_in,
                              void* d_out, int out_size) {
    const float* h   = (const float*)d_in[0];
    const int*   src = (const int*)d_in[1];
    const int*   dst = (const int*)d_in[2];
    const float* W1  = (const float*)d_in[3];
    const float* b1  = (const float*)d_in[4];
    const float* Wc1 = (const float*)d_in[5];
    const float* bc1 = (const float*)d_in[6];
    const float* Wc2 = (const float*)d_in[7];
    const float* bc2 = (const float*)d_in[8];

    int n_nodes = in_sizes[0] / DIM;
    int n_edges = in_sizes[1];
    int n4 = n_edges / 4;

    static bool s_init = false;
    if (!s_init) {
        cudaFuncSetAttribute(fused_kernel,
                             cudaFuncAttributeMaxDynamicSharedMemorySize, 98304);
        s_init = true;
    }

    void *do_p = nullptr, *di_p = nullptr, *hs_p = nullptr, *y_p = nullptr;
    cudaGetSymbolAddress(&do_p, g_deg_out);
    cudaGetSymbolAddress(&di_p, g_deg_in);
    cudaGetSymbolAddress(&hs_p, g_hsum);
    cudaGetSymbolAddress(&y_p, g_y);

    cudaMemsetAsync(do_p, 0, (size_t)n_nodes * sizeof(int));
    cudaMemsetAsync(di_p, 0, (size_t)n_nodes * sizeof(int));
    cudaMemsetAsync(hs_p, 0, DIM * sizeof(float));

    deg_kernel<<<(n4 + 255) / 256, 256>>>((const int4*)src, (const int4*)dst,
                                          src, dst, n4, n_edges);

    int nb = (n_nodes + SCAN_BLK - 1) / SCAN_BLK;
    scan1_kernel<<<nb, SCAN_BLK>>>(n_nodes);
    scan2_kernel<<<1, 256>>>(nb);
    scan3_kernel<<<(n_nodes + 255) / 256, 256>>>(n_nodes, n_edges);

    int n4e = n_nodes * 32;   // float4 elements in feature matrix
    prescale_kernel<<<(n4e + 255) / 256, 256>>>((const float4*)h, n4e);

    fill_kernel<<<(n4 + 255) / 256, 256>>>((const int4*)src, (const int4*)dst,
                                           src, dst, n4, n_edges);

    fused_kernel<<<296, 256, 98304>>>((const float4*)y_p, W1, b1, n_nodes);

    head_kernel<<<1, 128>>>(Wc1, bc1, Wc2, bc2, (float*)d_out, 1.0f / (float)n_nodes);
}

// round 8
// speedup vs baseline: 1.0379x; 1.0379x over previous
#include <cuda_runtime.h>
#include <cuda_bf16.h>
#include <cstdint>

#define DIM 128
#define NMAX 100000
#define EMAX 1600000
#define SCAN_BLK 1024
#define GW 8    // warps per block in fused kernel
#define MB 8    // nodes per warp-batch in fused kernel

// Scratch (device globals: allocation-free per harness rules)
__device__ __nv_bfloat16 g_yb[(size_t)NMAX * DIM];  // prescaled h * inv_out, bf16
__device__ int   g_deg_out[NMAX];
__device__ int   g_deg_in[NMAX];
__device__ float g_inv_in[NMAX];
__device__ int   g_row_ptr[NMAX + 1];
__device__ int   g_cursor[NMAX];
__device__ int   g_csr_src[EMAX];
__device__ int   g_blksum[256];
__device__ int   g_blkoff[256];
__device__ int   g_scan_tmp[NMAX];
__device__ float g_hsum[DIM];

__device__ __forceinline__ __nv_bfloat162 u2bf2(unsigned u) {
    return *reinterpret_cast<__nv_bfloat162*>(&u);
}

// ---------------------------------------------------------------------------
// 1) degree counting, vectorized 4 edges/thread
// ---------------------------------------------------------------------------
__global__ void deg_kernel(const int4* __restrict__ src4, const int4* __restrict__ dst4,
                           const int* __restrict__ src, const int* __restrict__ dst,
                           int n4, int n_edges) {
    int i = blockIdx.x * blockDim.x + threadIdx.x;
    if (i < n4) {
        int4 s = src4[i];
        atomicAdd(&g_deg_out[s.x], 1); atomicAdd(&g_deg_out[s.y], 1);
        atomicAdd(&g_deg_out[s.z], 1); atomicAdd(&g_deg_out[s.w], 1);
        int4 d = dst4[i];
        atomicAdd(&g_deg_in[d.x], 1); atomicAdd(&g_deg_in[d.y], 1);
        atomicAdd(&g_deg_in[d.z], 1); atomicAdd(&g_deg_in[d.w], 1);
    }
    if (blockIdx.x == gridDim.x - 1 && threadIdx.x == blockDim.x - 1) {
        for (int e = n4 * 4; e < n_edges; e++) {
            atomicAdd(&g_deg_out[src[e]], 1);
            atomicAdd(&g_deg_in[dst[e]], 1);
        }
    }
}

// ---------------------------------------------------------------------------
// 2) exclusive scan of deg_in -> row_ptr (2-level scan)
// ---------------------------------------------------------------------------
__global__ void scan1_kernel(int n) {
    __shared__ int sm[SCAN_BLK];
    int i = blockIdx.x * SCAN_BLK + threadIdx.x;
    int v = (i < n) ? g_deg_in[i] : 0;
    sm[threadIdx.x] = v;
    __syncthreads();
#pragma unroll
    for (int off = 1; off < SCAN_BLK; off <<= 1) {
        int t = (threadIdx.x >= off) ? sm[threadIdx.x - off] : 0;
        __syncthreads();
        sm[threadIdx.x] += t;
        __syncthreads();
    }
    if (i < n) g_scan_tmp[i] = sm[threadIdx.x] - v;   // exclusive
    if (threadIdx.x == SCAN_BLK - 1) g_blksum[blockIdx.x] = sm[SCAN_BLK - 1];
}

__global__ void scan2_kernel(int nb) {
    __shared__ int sm[256];
    int t = threadIdx.x;
    int v = (t < nb) ? g_blksum[t] : 0;
    sm[t] = v;
    __syncthreads();
#pragma unroll
    for (int off = 1; off < 256; off <<= 1) {
        int u = (t >= off) ? sm[t - off] : 0;
        __syncthreads();
        sm[t] += u;
        __syncthreads();
    }
    if (t < nb) g_blkoff[t] = sm[t] - v;   // exclusive
}

// ---------------------------------------------------------------------------
// 3) merged: row_ptr/cursor/inv_in finalize + bf16 prescale of features.
//    One warp (32 threads) per node; lane handles one float4 (4 elems).
// ---------------------------------------------------------------------------
__global__ void scan3p_kernel(const float4* __restrict__ h4, int n, int n_edges) {
    int t = blockIdx.x * blockDim.x + threadIdx.x;
    int node = t >> 5, lane = t & 31;
    if (node >= n) return;
    float sc = rsqrtf((float)(g_deg_out[node] + 1));
    float4 v = h4[(size_t)node * 32 + lane];
    __nv_bfloat162 lo = __floats2bfloat162_rn(v.x * sc, v.y * sc);
    __nv_bfloat162 hi = __floats2bfloat162_rn(v.z * sc, v.w * sc);
    uint2 pk;
    pk.x = *reinterpret_cast<unsigned*>(&lo);
    pk.y = *reinterpret_cast<unsigned*>(&hi);
    ((uint2*)g_yb)[(size_t)node * 32 + lane] = pk;
    if (lane == 0) {
        int r = g_scan_tmp[node] + g_blkoff[node / SCAN_BLK];
        g_row_ptr[node] = r;
        g_cursor[node] = r;
        g_inv_in[node] = rsqrtf((float)(g_deg_in[node] + 1));
    }
    if (t == 0) g_row_ptr[n] = n_edges;
}

// ---------------------------------------------------------------------------
// 4) bucket fill: csr_src grouped by dst (4 edges/thread)
// ---------------------------------------------------------------------------
__global__ void fill_kernel(const int4* __restrict__ src4, const int4* __restrict__ dst4,
                            const int* __restrict__ src, const int* __restrict__ dst,
                            int n4, int n_edges) {
    int i = blockIdx.x * blockDim.x + threadIdx.x;
    if (i < n4) {
        int4 s = src4[i];
        int4 d = dst4[i];
        g_csr_src[atomicAdd(&g_cursor[d.x], 1)] = s.x;
        g_csr_src[atomicAdd(&g_cursor[d.y], 1)] = s.y;
        g_csr_src[atomicAdd(&g_cursor[d.z], 1)] = s.z;
        g_csr_src[atomicAdd(&g_cursor[d.w], 1)] = s.w;
    }
    if (blockIdx.x == gridDim.x - 1 && threadIdx.x == blockDim.x - 1) {
        for (int e = n4 * 4; e < n_edges; e++)
            g_csr_src[atomicAdd(&g_cursor[dst[e]], 1)] = src[e];
    }
}

// ---------------------------------------------------------------------------
// 5) FUSED: per warp-batch of MB dst rows:
//      a) x[d] = (y[d] + sum_s y[s]) * wi[d] -> smem.  y rows are bf16
//         (256B/row, LDG.64/lane); indices coalesced + shfl-broadcast;
//         bf16x2 HADD2 accumulation; MLP-8 unroll.
//      b) GEMV y = relu(x @ W1 + b1) in fp32, K-paired f32x2 accumulators,
//         node-sum into g_hsum.
// ---------------------------------------------------------------------------
__global__ __launch_bounds__(256, 2)
void fused_kernel(const float* __restrict__ W1, const float* __restrict__ b1,
                  int n_nodes) {
    extern __shared__ float4 dyn[];
    float4* Wp   = dyn;          // [32][128] float4 = 64KB
    float4* xbuf = dyn + 4096;   // [GW][MB][32] float4 = 32KB

    for (int idx = threadIdx.x; idx < 4096; idx += blockDim.x) {
        int t2 = idx >> 7, j = idx & 127;
        Wp[idx] = make_float4(W1[(4 * t2 + 0) * 128 + j],
                              W1[(4 * t2 + 1) * 128 + j],
                              W1[(4 * t2 + 2) * 128 + j],
                              W1[(4 * t2 + 3) * 128 + j]);
    }
    __syncthreads();

    int lane = threadIdx.x & 31;
    int w    = threadIdx.x >> 5;
    int warp = blockIdx.x * GW + w;
    int nwarp = gridDim.x * GW;

    float bb[4], s[4];
#pragma unroll
    for (int c = 0; c < 4; c++) {
        bb[c] = b1[c * 32 + lane];
        s[c] = 0.f;
    }

    const ulonglong2* Wp2 = (const ulonglong2*)Wp;
    float4* xw = &xbuf[w * MB * 32];
    const ulonglong2* xb = (const ulonglong2*)xw;
    const uint2* yb = (const uint2*)g_yb;

    for (int base = warp * MB; base < n_nodes; base += nwarp * MB) {
        // ---- phase A: aggregate MB rows into xw ----
        for (int m = 0; m < MB; m++) {
            int d = base + m;
            float4 out = make_float4(0.f, 0.f, 0.f, 0.f);
            if (d < n_nodes) {
                uint2 p = __ldg(&yb[(size_t)d * 32 + lane]);   // self loop
                __nv_bfloat162 a0l = u2bf2(p.x), a0h = u2bf2(p.y);
                __nv_bfloat162 z = __float2bfloat162_rn(0.f);
                __nv_bfloat162 a1l = z, a1h = z, a2l = z, a2h = z, a3l = z, a3h = z;
                int beg = g_row_ptr[d], end = g_row_ptr[d + 1];
                for (int i0 = beg; i0 < end; i0 += 32) {
                    int cnt = min(32, end - i0);
                    int e = i0 + lane;
                    int idx = (e < end) ? g_csr_src[e] : 0;   // coalesced
                    int j = 0;
                    for (; j + 8 <= cnt; j += 8) {
                        int s0 = __shfl_sync(0xffffffffu, idx, j + 0);
                        int s1 = __shfl_sync(0xffffffffu, idx, j + 1);
                        int s2 = __shfl_sync(0xffffffffu, idx, j + 2);
                        int s3 = __shfl_sync(0xffffffffu, idx, j + 3);
                        int s4 = __shfl_sync(0xffffffffu, idx, j + 4);
                        int s5 = __shfl_sync(0xffffffffu, idx, j + 5);
                        int s6 = __shfl_sync(0xffffffffu, idx, j + 6);
                        int s7 = __shfl_sync(0xffffffffu, idx, j + 7);
                        uint2 q0 = __ldg(&yb[(size_t)s0 * 32 + lane]);
                        uint2 q1 = __ldg(&yb[(size_t)s1 * 32 + lane]);
                        uint2 q2 = __ldg(&yb[(size_t)s2 * 32 + lane]);
                        uint2 q3 = __ldg(&yb[(size_t)s3 * 32 + lane]);
                        uint2 q4 = __ldg(&yb[(size_t)s4 * 32 + lane]);
                        uint2 q5 = __ldg(&yb[(size_t)s5 * 32 + lane]);
                        uint2 q6 = __ldg(&yb[(size_t)s6 * 32 + lane]);
                        uint2 q7 = __ldg(&yb[(size_t)s7 * 32 + lane]);
                        a0l = __hadd2(a0l, u2bf2(q0.x)); a0h = __hadd2(a0h, u2bf2(q0.y));
                        a1l = __hadd2(a1l, u2bf2(q1.x)); a1h = __hadd2(a1h, u2bf2(q1.y));
                        a2l = __hadd2(a2l, u2bf2(q2.x)); a2h = __hadd2(a2h, u2bf2(q2.y));
                        a3l = __hadd2(a3l, u2bf2(q3.x)); a3h = __hadd2(a3h, u2bf2(q3.y));
                        a0l = __hadd2(a0l, u2bf2(q4.x)); a0h = __hadd2(a0h, u2bf2(q4.y));
                        a1l = __hadd2(a1l, u2bf2(q5.x)); a1h = __hadd2(a1h, u2bf2(q5.y));
                        a2l = __hadd2(a2l, u2bf2(q6.x)); a2h = __hadd2(a2h, u2bf2(q6.y));
                        a3l = __hadd2(a3l, u2bf2(q7.x)); a3h = __hadd2(a3h, u2bf2(q7.y));
                    }
                    if (j + 4 <= cnt) {
                        int s0 = __shfl_sync(0xffffffffu, idx, j + 0);
                        int s1 = __shfl_sync(0xffffffffu, idx, j + 1);
                        int s2 = __shfl_sync(0xffffffffu, idx, j + 2);
                        int s3 = __shfl_sync(0xffffffffu, idx, j + 3);
                        uint2 q0 = __ldg(&yb[(size_t)s0 * 32 + lane]);
                        uint2 q1 = __ldg(&yb[(size_t)s1 * 32 + lane]);
                        uint2 q2 = __ldg(&yb[(size_t)s2 * 32 + lane]);
                        uint2 q3 = __ldg(&yb[(size_t)s3 * 32 + lane]);
                        a0l = __hadd2(a0l, u2bf2(q0.x)); a0h = __hadd2(a0h, u2bf2(q0.y));
                        a1l = __hadd2(a1l, u2bf2(q1.x)); a1h = __hadd2(a1h, u2bf2(q1.y));
                        a2l = __hadd2(a2l, u2bf2(q2.x)); a2h = __hadd2(a2h, u2bf2(q2.y));
                        a3l = __hadd2(a3l, u2bf2(q3.x)); a3h = __hadd2(a3h, u2bf2(q3.y));
                        j += 4;
                    }
                    for (; j < cnt; j++) {
                        int s0 = __shfl_sync(0xffffffffu, idx, j);
                        uint2 q0 = __ldg(&yb[(size_t)s0 * 32 + lane]);
                        a0l = __hadd2(a0l, u2bf2(q0.x)); a0h = __hadd2(a0h, u2bf2(q0.y));
                    }
                }
                float wi = g_inv_in[d];
                float2 f0 = __bfloat1622float2(a0l), f1 = __bfloat1622float2(a1l);
                float2 f2 = __bfloat1622float2(a2l), f3 = __bfloat1622float2(a3l);
                float2 g0 = __bfloat1622float2(a0h), g1 = __bfloat1622float2(a1h);
                float2 g2 = __bfloat1622float2(a2h), g3 = __bfloat1622float2(a3h);
                out.x = (f0.x + f1.x + f2.x + f3.x) * wi;
                out.y = (f0.y + f1.y + f2.y + f3.y) * wi;
                out.z = (g0.x + g1.x + g2.x + g3.x) * wi;
                out.w = (g0.y + g1.y + g2.y + g3.y) * wi;
            }
            xw[m * 32 + lane] = out;
        }
        __syncwarp();

        // ---- phase B: GEMV over the MB staged rows ----
        unsigned long long acc[MB][4];
#pragma unroll
        for (int m = 0; m < MB; m++)
#pragma unroll
            for (int c = 0; c < 4; c++) acc[m][c] = 0ull;

#pragma unroll 2
        for (int t2 = 0; t2 < 32; t2++) {
            ulonglong2 wv[4];
#pragma unroll
            for (int c = 0; c < 4; c++)
                wv[c] = Wp2[t2 * 128 + c * 32 + lane];
#pragma unroll
            for (int m = 0; m < MB; m++) {
                ulonglong2 xm = xb[m * 32 + t2];   // broadcast
#pragma unroll
                for (int c = 0; c < 4; c++) {
                    asm("fma.rn.f32x2 %0, %1, %2, %0;"
                        : "+l"(acc[m][c]) : "l"(wv[c].x), "l"(xm.x));
                    asm("fma.rn.f32x2 %0, %1, %2, %0;"
                        : "+l"(acc[m][c]) : "l"(wv[c].y), "l"(xm.y));
                }
            }
        }

#pragma unroll
        for (int m = 0; m < MB; m++) {
            if (base + m >= n_nodes) break;
#pragma unroll
            for (int c = 0; c < 4; c++) {
                unsigned lo, hi;
                asm("mov.b64 {%0, %1}, %2;" : "=r"(lo), "=r"(hi) : "l"(acc[m][c]));
                float y = __uint_as_float(lo) + __uint_as_float(hi) + bb[c];
                s[c] += fmaxf(y, 0.f);
            }
        }
        __syncwarp();   // xbuf reuse safety
    }

#pragma unroll
    for (int c = 0; c < 4; c++)
        atomicAdd(&g_hsum[c * 32 + lane], s[c]);
}

// ---------------------------------------------------------------------------
// 6) classifier heads, split-K over 4 warps
// ---------------------------------------------------------------------------
__global__ void head_kernel(const float* __restrict__ Wc1, const float* __restrict__ bc1,
                            const float* __restrict__ Wc2, const float* __restrict__ bc2,
                            float* __restrict__ out, float inv_n) {
    __shared__ float red[128];
    int t = threadIdx.x;          // 0..127
    int o = t & 31;               // output index
    int part = t >> 5;            // k-quarter
    const float* Wc = (o < 16) ? Wc1 : Wc2;
    int c = o & 15;
    float acc = 0.f;
#pragma unroll 8
    for (int k = part * 32; k < part * 32 + 32; k++)
        acc += g_hsum[k] * Wc[k * 16 + c];
    red[t] = acc;
    __syncthreads();
    if (t < 32) {
        const float* bc = (t < 16) ? bc1 : bc2;
        float v = red[t] + red[t + 32] + red[t + 64] + red[t + 96];
        out[t] = v * inv_n + bc[c];
    }
}

// ---------------------------------------------------------------------------
extern "C" void kernel_launch(void* const* d_in, const int* in_sizes, int n_in,
                              void* d_out, int out_size) {
    const float* h   = (const float*)d_in[0];
    const int*   src = (const int*)d_in[1];
    const int*   dst = (const int*)d_in[2];
    const float* W1  = (const float*)d_in[3];
    const float* b1  = (const float*)d_in[4];
    const float* Wc1 = (const float*)d_in[5];
    const float* bc1 = (const float*)d_in[6];
    const float* Wc2 = (const float*)d_in[7];
    const float* bc2 = (const float*)d_in[8];

    int n_nodes = in_sizes[0] / DIM;
    int n_edges = in_sizes[1];
    int n4 = n_edges / 4;

    static bool s_init = false;
    if (!s_init) {
        cudaFuncSetAttribute(fused_kernel,
                             cudaFuncAttributeMaxDynamicSharedMemorySize, 98304);
        s_init = true;
    }

    void *do_p = nullptr, *di_p = nullptr, *hs_p = nullptr;
    cudaGetSymbolAddress(&do_p, g_deg_out);
    cudaGetSymbolAddress(&di_p, g_deg_in);
    cudaGetSymbolAddress(&hs_p, g_hsum);

    cudaMemsetAsync(do_p, 0, (size_t)n_nodes * sizeof(int));
    cudaMemsetAsync(di_p, 0, (size_t)n_nodes * sizeof(int));
    cudaMemsetAsync(hs_p, 0, DIM * sizeof(float));

    deg_kernel<<<(n4 + 255) / 256, 256>>>((const int4*)src, (const int4*)dst,
                                          src, dst, n4, n_edges);

    int nb = (n_nodes + SCAN_BLK - 1) / SCAN_BLK;
    scan1_kernel<<<nb, SCAN_BLK>>>(n_nodes);
    scan2_kernel<<<1, 256>>>(nb);

    // merged finalize + bf16 prescale: one warp per node
    long long nthr = (long long)n_nodes * 32;
    int nblk = (int)((nthr + 255) / 256);
    scan3p_kernel<<<nblk, 256>>>((const float4*)h, n_nodes, n_edges);

    fill_kernel<<<(n4 + 255) / 256, 256>>>((const int4*)src, (const int4*)dst,
                                           src, dst, n4, n_edges);

    fused_kernel<<<296, 256, 98304>>>(W1, b1, n_nodes);

    head_kernel<<<1, 128>>>(Wc1, bc1, Wc2, bc2, (float*)d_out, 1.0f / (float)n_nodes);
}

// round 9
// speedup vs baseline: 1.2068x; 1.1627x over previous
#include <cuda_runtime.h>
#include <cuda_bf16.h>
#include <cstdint>

#define DIM 128
#define NMAX 100000
#define EMAX 1600000
#define SCAN_BLK 1024
#define GW 8    // warps per block in gemv kernel
#define MB 8    // nodes per warp-batch in gemv kernel

// Scratch (device globals: allocation-free per harness rules)
__device__ __nv_bfloat16 g_yb[(size_t)NMAX * DIM];  // prescaled h * inv_out, bf16
__device__ __nv_bfloat16 g_xb[(size_t)NMAX * DIM];  // aggregated conv input, bf16
// zero-initialized block: one memset covers all three
__device__ struct { int deg_out[NMAX]; int deg_in[NMAX]; float hsum[DIM]; } g_z;
__device__ float g_inv_in[NMAX];
__device__ int   g_row_ptr[NMAX + 1];
__device__ int   g_cursor[NMAX];
__device__ int   g_csr_src[EMAX];
__device__ int   g_blksum[256];
__device__ int   g_blkoff[256];
__device__ int   g_scan_tmp[NMAX];

__device__ __forceinline__ __nv_bfloat162 u2bf2(unsigned u) {
    return *reinterpret_cast<__nv_bfloat162*>(&u);
}

// ---------------------------------------------------------------------------
// 1) degree counting, vectorized 4 edges/thread
// ---------------------------------------------------------------------------
__global__ void deg_kernel(const int4* __restrict__ src4, const int4* __restrict__ dst4,
                           const int* __restrict__ src, const int* __restrict__ dst,
                           int n4, int n_edges) {
    int i = blockIdx.x * blockDim.x + threadIdx.x;
    if (i < n4) {
        int4 s = src4[i];
        atomicAdd(&g_z.deg_out[s.x], 1); atomicAdd(&g_z.deg_out[s.y], 1);
        atomicAdd(&g_z.deg_out[s.z], 1); atomicAdd(&g_z.deg_out[s.w], 1);
        int4 d = dst4[i];
        atomicAdd(&g_z.deg_in[d.x], 1); atomicAdd(&g_z.deg_in[d.y], 1);
        atomicAdd(&g_z.deg_in[d.z], 1); atomicAdd(&g_z.deg_in[d.w], 1);
    }
    if (blockIdx.x == gridDim.x - 1 && threadIdx.x == blockDim.x - 1) {
        for (int e = n4 * 4; e < n_edges; e++) {
            atomicAdd(&g_z.deg_out[src[e]], 1);
            atomicAdd(&g_z.deg_in[dst[e]], 1);
        }
    }
}

// ---------------------------------------------------------------------------
// 2) exclusive scan of deg_in -> row_ptr (2-level scan)
// ---------------------------------------------------------------------------
__global__ void scan1_kernel(int n) {
    __shared__ int sm[SCAN_BLK];
    int i = blockIdx.x * SCAN_BLK + threadIdx.x;
    int v = (i < n) ? g_z.deg_in[i] : 0;
    sm[threadIdx.x] = v;
    __syncthreads();
#pragma unroll
    for (int off = 1; off < SCAN_BLK; off <<= 1) {
        int t = (threadIdx.x >= off) ? sm[threadIdx.x - off] : 0;
        __syncthreads();
        sm[threadIdx.x] += t;
        __syncthreads();
    }
    if (i < n) g_scan_tmp[i] = sm[threadIdx.x] - v;   // exclusive
    if (threadIdx.x == SCAN_BLK - 1) g_blksum[blockIdx.x] = sm[SCAN_BLK - 1];
}

__global__ void scan2_kernel(int nb) {
    __shared__ int sm[256];
    int t = threadIdx.x;
    int v = (t < nb) ? g_blksum[t] : 0;
    sm[t] = v;
    __syncthreads();
#pragma unroll
    for (int off = 1; off < 256; off <<= 1) {
        int u = (t >= off) ? sm[t - off] : 0;
        __syncthreads();
        sm[t] += u;
        __syncthreads();
    }
    if (t < nb) g_blkoff[t] = sm[t] - v;   // exclusive
}

// ---------------------------------------------------------------------------
// 3) merged: row_ptr/cursor/inv_in finalize + bf16 prescale of features.
//    One warp per node; lane handles one float4 (4 elems).
// ---------------------------------------------------------------------------
__global__ void scan3p_kernel(const float4* __restrict__ h4, int n, int n_edges) {
    int t = blockIdx.x * blockDim.x + threadIdx.x;
    int node = t >> 5, lane = t & 31;
    if (node >= n) return;
    float sc = rsqrtf((float)(g_z.deg_out[node] + 1));
    float4 v = h4[(size_t)node * 32 + lane];
    __nv_bfloat162 lo = __floats2bfloat162_rn(v.x * sc, v.y * sc);
    __nv_bfloat162 hi = __floats2bfloat162_rn(v.z * sc, v.w * sc);
    uint2 pk;
    pk.x = *reinterpret_cast<unsigned*>(&lo);
    pk.y = *reinterpret_cast<unsigned*>(&hi);
    ((uint2*)g_yb)[(size_t)node * 32 + lane] = pk;
    if (lane == 0) {
        int r = g_scan_tmp[node] + g_blkoff[node / SCAN_BLK];
        g_row_ptr[node] = r;
        g_cursor[node] = r;
        g_inv_in[node] = rsqrtf((float)(g_z.deg_in[node] + 1));
    }
    if (t == 0) g_row_ptr[n] = n_edges;
}

// ---------------------------------------------------------------------------
// 4) bucket fill: csr_src grouped by dst (4 edges/thread)
// ---------------------------------------------------------------------------
__global__ void fill_kernel(const int4* __restrict__ src4, const int4* __restrict__ dst4,
                            const int* __restrict__ src, const int* __restrict__ dst,
                            int n4, int n_edges) {
    int i = blockIdx.x * blockDim.x + threadIdx.x;
    if (i < n4) {
        int4 s = src4[i];
        int4 d = dst4[i];
        g_csr_src[atomicAdd(&g_cursor[d.x], 1)] = s.x;
        g_csr_src[atomicAdd(&g_cursor[d.y], 1)] = s.y;
        g_csr_src[atomicAdd(&g_cursor[d.z], 1)] = s.z;
        g_csr_src[atomicAdd(&g_cursor[d.w], 1)] = s.w;
    }
    if (blockIdx.x == gridDim.x - 1 && threadIdx.x == blockDim.x - 1) {
        for (int e = n4 * 4; e < n_edges; e++)
            g_csr_src[atomicAdd(&g_cursor[dst[e]], 1)] = src[e];
    }
}

// ---------------------------------------------------------------------------
// 5) AGG: one warp per dst node, NO smem -> full occupancy, latency hidden.
//    x[d] = (y[d] + sum_s y[s]) * wi[d], all bf16 traffic, written bf16.
// ---------------------------------------------------------------------------
__global__ __launch_bounds__(256)
void agg_kernel(int n_nodes) {
    int t = blockIdx.x * blockDim.x + threadIdx.x;
    int d = t >> 5, lane = t & 31;
    if (d >= n_nodes) return;

    const uint2* yb = (const uint2*)g_yb;
    uint2 p = __ldg(&yb[(size_t)d * 32 + lane]);   // self loop
    __nv_bfloat162 a0l = u2bf2(p.x), a0h = u2bf2(p.y);
    __nv_bfloat162 z = __float2bfloat162_rn(0.f);
    __nv_bfloat162 a1l = z, a1h = z, a2l = z, a2h = z, a3l = z, a3h = z;

    int beg = g_row_ptr[d], end = g_row_ptr[d + 1];
    for (int i0 = beg; i0 < end; i0 += 32) {
        int cnt = min(32, end - i0);
        int e = i0 + lane;
        int idx = (e < end) ? g_csr_src[e] : 0;   // coalesced
        int j = 0;
        for (; j + 8 <= cnt; j += 8) {
            int s0 = __shfl_sync(0xffffffffu, idx, j + 0);
            int s1 = __shfl_sync(0xffffffffu, idx, j + 1);
            int s2 = __shfl_sync(0xffffffffu, idx, j + 2);
            int s3 = __shfl_sync(0xffffffffu, idx, j + 3);
            int s4 = __shfl_sync(0xffffffffu, idx, j + 4);
            int s5 = __shfl_sync(0xffffffffu, idx, j + 5);
            int s6 = __shfl_sync(0xffffffffu, idx, j + 6);
            int s7 = __shfl_sync(0xffffffffu, idx, j + 7);
            uint2 q0 = __ldg(&yb[(size_t)s0 * 32 + lane]);
            uint2 q1 = __ldg(&yb[(size_t)s1 * 32 + lane]);
            uint2 q2 = __ldg(&yb[(size_t)s2 * 32 + lane]);
            uint2 q3 = __ldg(&yb[(size_t)s3 * 32 + lane]);
            uint2 q4 = __ldg(&yb[(size_t)s4 * 32 + lane]);
            uint2 q5 = __ldg(&yb[(size_t)s5 * 32 + lane]);
            uint2 q6 = __ldg(&yb[(size_t)s6 * 32 + lane]);
            uint2 q7 = __ldg(&yb[(size_t)s7 * 32 + lane]);
            a0l = __hadd2(a0l, u2bf2(q0.x)); a0h = __hadd2(a0h, u2bf2(q0.y));
            a1l = __hadd2(a1l, u2bf2(q1.x)); a1h = __hadd2(a1h, u2bf2(q1.y));
            a2l = __hadd2(a2l, u2bf2(q2.x)); a2h = __hadd2(a2h, u2bf2(q2.y));
            a3l = __hadd2(a3l, u2bf2(q3.x)); a3h = __hadd2(a3h, u2bf2(q3.y));
            a0l = __hadd2(a0l, u2bf2(q4.x)); a0h = __hadd2(a0h, u2bf2(q4.y));
            a1l = __hadd2(a1l, u2bf2(q5.x)); a1h = __hadd2(a1h, u2bf2(q5.y));
            a2l = __hadd2(a2l, u2bf2(q6.x)); a2h = __hadd2(a2h, u2bf2(q6.y));
            a3l = __hadd2(a3l, u2bf2(q7.x)); a3h = __hadd2(a3h, u2bf2(q7.y));
        }
        if (j + 4 <= cnt) {
            int s0 = __shfl_sync(0xffffffffu, idx, j + 0);
            int s1 = __shfl_sync(0xffffffffu, idx, j + 1);
            int s2 = __shfl_sync(0xffffffffu, idx, j + 2);
            int s3 = __shfl_sync(0xffffffffu, idx, j + 3);
            uint2 q0 = __ldg(&yb[(size_t)s0 * 32 + lane]);
            uint2 q1 = __ldg(&yb[(size_t)s1 * 32 + lane]);
            uint2 q2 = __ldg(&yb[(size_t)s2 * 32 + lane]);
            uint2 q3 = __ldg(&yb[(size_t)s3 * 32 + lane]);
            a0l = __hadd2(a0l, u2bf2(q0.x)); a0h = __hadd2(a0h, u2bf2(q0.y));
            a1l = __hadd2(a1l, u2bf2(q1.x)); a1h = __hadd2(a1h, u2bf2(q1.y));
            a2l = __hadd2(a2l, u2bf2(q2.x)); a2h = __hadd2(a2h, u2bf2(q2.y));
            a3l = __hadd2(a3l, u2bf2(q3.x)); a3h = __hadd2(a3h, u2bf2(q3.y));
            j += 4;
        }
        for (; j < cnt; j++) {
            int s0 = __shfl_sync(0xffffffffu, idx, j);
            uint2 q0 = __ldg(&yb[(size_t)s0 * 32 + lane]);
            a0l = __hadd2(a0l, u2bf2(q0.x)); a0h = __hadd2(a0h, u2bf2(q0.y));
        }
    }

    float wi = g_inv_in[d];
    float2 f0 = __bfloat1622float2(a0l), f1 = __bfloat1622float2(a1l);
    float2 f2 = __bfloat1622float2(a2l), f3 = __bfloat1622float2(a3l);
    float2 g0 = __bfloat1622float2(a0h), g1 = __bfloat1622float2(a1h);
    float2 g2 = __bfloat1622float2(a2h), g3 = __bfloat1622float2(a3h);
    float ox = (f0.x + f1.x + f2.x + f3.x) * wi;
    float oy = (f0.y + f1.y + f2.y + f3.y) * wi;
    float oz = (g0.x + g1.x + g2.x + g3.x) * wi;
    float ow = (g0.y + g1.y + g2.y + g3.y) * wi;
    __nv_bfloat162 lo = __floats2bfloat162_rn(ox, oy);
    __nv_bfloat162 hi = __floats2bfloat162_rn(oz, ow);
    uint2 pk;
    pk.x = *reinterpret_cast<unsigned*>(&lo);
    pk.y = *reinterpret_cast<unsigned*>(&hi);
    ((uint2*)g_xb)[(size_t)d * 32 + lane] = pk;
}

// ---------------------------------------------------------------------------
// 6) GEMV + relu + mean-sum over x (bf16, sequential reads).
//    Weights in smem (fp32); K-paired f32x2 accumulators; MB=8 nodes/warp.
// ---------------------------------------------------------------------------
__global__ __launch_bounds__(256, 2)
void gemv_kernel(const float* __restrict__ W1, const float* __restrict__ b1,
                 int n_nodes) {
    extern __shared__ float4 dyn[];
    float4* Wp   = dyn;          // [32][128] float4 = 64KB
    float4* xbuf = dyn + 4096;   // [GW][MB][32] float4 = 32KB

    for (int idx = threadIdx.x; idx < 4096; idx += blockDim.x) {
        int t2 = idx >> 7, j = idx & 127;
        Wp[idx] = make_float4(W1[(4 * t2 + 0) * 128 + j],
                              W1[(4 * t2 + 1) * 128 + j],
                              W1[(4 * t2 + 2) * 128 + j],
                              W1[(4 * t2 + 3) * 128 + j]);
    }
    __syncthreads();

    int lane = threadIdx.x & 31;
    int w    = threadIdx.x >> 5;
    int warp = blockIdx.x * GW + w;
    int nwarp = gridDim.x * GW;

    float bb[4], s[4];
#pragma unroll
    for (int c = 0; c < 4; c++) {
        bb[c] = b1[c * 32 + lane];
        s[c] = 0.f;
    }

    const ulonglong2* Wp2 = (const ulonglong2*)Wp;
    float4* xw = &xbuf[w * MB * 32];
    const ulonglong2* xb = (const ulonglong2*)xw;
    const uint2* xg = (const uint2*)g_xb;

    for (int base = warp * MB; base < n_nodes; base += nwarp * MB) {
        __syncwarp();
#pragma unroll
        for (int m = 0; m < MB; m++) {
            int n = base + m;
            float4 v = make_float4(0.f, 0.f, 0.f, 0.f);
            if (n < n_nodes) {
                uint2 p = __ldg(&xg[(size_t)n * 32 + lane]);
                float2 lo = __bfloat1622float2(u2bf2(p.x));
                float2 hi = __bfloat1622float2(u2bf2(p.y));
                v = make_float4(lo.x, lo.y, hi.x, hi.y);
            }
            xw[m * 32 + lane] = v;
        }
        __syncwarp();

        unsigned long long acc[MB][4];
#pragma unroll
        for (int m = 0; m < MB; m++)
#pragma unroll
            for (int c = 0; c < 4; c++) acc[m][c] = 0ull;

#pragma unroll 2
        for (int t2 = 0; t2 < 32; t2++) {
            ulonglong2 wv[4];
#pragma unroll
            for (int c = 0; c < 4; c++)
                wv[c] = Wp2[t2 * 128 + c * 32 + lane];
#pragma unroll
            for (int m = 0; m < MB; m++) {
                ulonglong2 xm = xb[m * 32 + t2];   // broadcast
#pragma unroll
                for (int c = 0; c < 4; c++) {
                    asm("fma.rn.f32x2 %0, %1, %2, %0;"
                        : "+l"(acc[m][c]) : "l"(wv[c].x), "l"(xm.x));
                    asm("fma.rn.f32x2 %0, %1, %2, %0;"
                        : "+l"(acc[m][c]) : "l"(wv[c].y), "l"(xm.y));
                }
            }
        }

#pragma unroll
        for (int m = 0; m < MB; m++) {
            if (base + m >= n_nodes) break;
#pragma unroll
            for (int c = 0; c < 4; c++) {
                unsigned lo, hi;
                asm("mov.b64 {%0, %1}, %2;" : "=r"(lo), "=r"(hi) : "l"(acc[m][c]));
                float y = __uint_as_float(lo) + __uint_as_float(hi) + bb[c];
                s[c] += fmaxf(y, 0.f);
            }
        }
    }

#pragma unroll
    for (int c = 0; c < 4; c++)
        atomicAdd(&g_z.hsum[c * 32 + lane], s[c]);
}

// ---------------------------------------------------------------------------
// 7) classifier heads, split-K over 4 warps
// ---------------------------------------------------------------------------
__global__ void head_kernel(const float* __restrict__ Wc1, const float* __restrict__ bc1,
                            const float* __restrict__ Wc2, const float* __restrict__ bc2,
                            float* __restrict__ out, float inv_n) {
    __shared__ float red[128];
    int t = threadIdx.x;          // 0..127
    int o = t & 31;               // output index
    int part = t >> 5;            // k-quarter
    const float* Wc = (o < 16) ? Wc1 : Wc2;
    int c = o & 15;
    float acc = 0.f;
#pragma unroll 8
    for (int k = part * 32; k < part * 32 + 32; k++)
        acc += g_z.hsum[k] * Wc[k * 16 + c];
    red[t] = acc;
    __syncthreads();
    if (t < 32) {
        const float* bc = (t < 16) ? bc1 : bc2;
        float v = red[t] + red[t + 32] + red[t + 64] + red[t + 96];
        out[t] = v * inv_n + bc[c];
    }
}

// ---------------------------------------------------------------------------
extern "C" void kernel_launch(void* const* d_in, const int* in_sizes, int n_in,
                              void* d_out, int out_size) {
    const float* h   = (const float*)d_in[0];
    const int*   src = (const int*)d_in[1];
    const int*   dst = (const int*)d_in[2];
    const float* W1  = (const float*)d_in[3];
    const float* b1  = (const float*)d_in[4];
    const float* Wc1 = (const float*)d_in[5];
    const float* bc1 = (const float*)d_in[6];
    const float* Wc2 = (const float*)d_in[7];
    const float* bc2 = (const float*)d_in[8];

    int n_nodes = in_sizes[0] / DIM;
    int n_edges = in_sizes[1];
    int n4 = n_edges / 4;

    static bool s_init = false;
    if (!s_init) {
        cudaFuncSetAttribute(gemv_kernel,
                             cudaFuncAttributeMaxDynamicSharedMemorySize, 98304);
        s_init = true;
    }

    void* z_p = nullptr;
    cudaGetSymbolAddress(&z_p, g_z);
    cudaMemsetAsync(z_p, 0, sizeof(g_z));   // deg_out + deg_in + hsum, one call

    deg_kernel<<<(n4 + 255) / 256, 256>>>((const int4*)src, (const int4*)dst,
                                          src, dst, n4, n_edges);

    int nb = (n_nodes + SCAN_BLK - 1) / SCAN_BLK;
    scan1_kernel<<<nb, SCAN_BLK>>>(n_nodes);
    scan2_kernel<<<1, 256>>>(nb);

    long long nthr = (long long)n_nodes * 32;
    int nblk = (int)((nthr + 255) / 256);
    scan3p_kernel<<<nblk, 256>>>((const float4*)h, n_nodes, n_edges);

    fill_kernel<<<(n4 + 255) / 256, 256>>>((const int4*)src, (const int4*)dst,
                                           src, dst, n4, n_edges);

    agg_kernel<<<nblk, 256>>>(n_nodes);

    gemv_kernel<<<296, 256, 98304>>>(W1, b1, n_nodes);

    head_kernel<<<1, 128>>>(Wc1, bc1, Wc2, bc2, (float*)d_out, 1.0f / (float)n_nodes);
}

// round 10
// speedup vs baseline: 1.2083x; 1.0013x over previous
#include <cuda_runtime.h>
#include <cuda_bf16.h>
#include <cstdint>

#define DIM 128
#define NMAX 100000
#define EMAX 1600000
#define SCAN_BLK 1024
#define GW 8    // warps per block in gemv kernel
#define MB 8    // nodes per warp-batch in gemv kernel

// Scratch (device globals: allocation-free per harness rules)
__device__ __nv_bfloat16 g_yb[(size_t)NMAX * DIM];  // prescaled h * inv_out, bf16
__device__ __nv_bfloat16 g_xb[(size_t)NMAX * DIM];  // aggregated conv input, bf16
// zero-initialized block: one memset covers all three
__device__ struct { int deg_out[NMAX]; int deg_in[NMAX]; float hsum[DIM]; } g_z;
__device__ float g_inv_in[NMAX];
__device__ int   g_row_ptr[NMAX + 1];
__device__ int   g_cursor[NMAX];
__device__ int   g_csr_src[EMAX];
__device__ int   g_blksum[256];
__device__ int   g_blkoff[256];
__device__ int   g_scan_tmp[NMAX];

__device__ __forceinline__ __nv_bfloat162 u2bf2(unsigned u) {
    return *reinterpret_cast<__nv_bfloat162*>(&u);
}

// ---------------------------------------------------------------------------
// 1) degree counting, vectorized 4 edges/thread
// ---------------------------------------------------------------------------
__global__ void deg_kernel(const int4* __restrict__ src4, const int4* __restrict__ dst4,
                           const int* __restrict__ src, const int* __restrict__ dst,
                           int n4, int n_edges) {
    int i = blockIdx.x * blockDim.x + threadIdx.x;
    if (i < n4) {
        int4 s = src4[i];
        atomicAdd(&g_z.deg_out[s.x], 1); atomicAdd(&g_z.deg_out[s.y], 1);
        atomicAdd(&g_z.deg_out[s.z], 1); atomicAdd(&g_z.deg_out[s.w], 1);
        int4 d = dst4[i];
        atomicAdd(&g_z.deg_in[d.x], 1); atomicAdd(&g_z.deg_in[d.y], 1);
        atomicAdd(&g_z.deg_in[d.z], 1); atomicAdd(&g_z.deg_in[d.w], 1);
    }
    if (blockIdx.x == gridDim.x - 1 && threadIdx.x == blockDim.x - 1) {
        for (int e = n4 * 4; e < n_edges; e++) {
            atomicAdd(&g_z.deg_out[src[e]], 1);
            atomicAdd(&g_z.deg_in[dst[e]], 1);
        }
    }
}

// ---------------------------------------------------------------------------
// 2) exclusive scan of deg_in -> row_ptr (2-level scan)
// ---------------------------------------------------------------------------
__global__ void scan1_kernel(int n) {
    __shared__ int sm[SCAN_BLK];
    int i = blockIdx.x * SCAN_BLK + threadIdx.x;
    int v = (i < n) ? g_z.deg_in[i] : 0;
    sm[threadIdx.x] = v;
    __syncthreads();
#pragma unroll
    for (int off = 1; off < SCAN_BLK; off <<= 1) {
        int t = (threadIdx.x >= off) ? sm[threadIdx.x - off] : 0;
        __syncthreads();
        sm[threadIdx.x] += t;
        __syncthreads();
    }
    if (i < n) g_scan_tmp[i] = sm[threadIdx.x] - v;   // exclusive
    if (threadIdx.x == SCAN_BLK - 1) g_blksum[blockIdx.x] = sm[SCAN_BLK - 1];
}

__global__ void scan2_kernel(int nb) {
    __shared__ int sm[256];
    int t = threadIdx.x;
    int v = (t < nb) ? g_blksum[t] : 0;
    sm[t] = v;
    __syncthreads();
#pragma unroll
    for (int off = 1; off < 256; off <<= 1) {
        int u = (t >= off) ? sm[t - off] : 0;
        __syncthreads();
        sm[t] += u;
        __syncthreads();
    }
    if (t < nb) g_blkoff[t] = sm[t] - v;   // exclusive
}

// ---------------------------------------------------------------------------
// 3) merged: row_ptr/cursor/inv_in finalize + bf16 prescale of features.
//    One warp per node; lane handles one float4 (4 elems).
// ---------------------------------------------------------------------------
__global__ void scan3p_kernel(const float4* __restrict__ h4, int n, int n_edges) {
    int t = blockIdx.x * blockDim.x + threadIdx.x;
    int node = t >> 5, lane = t & 31;
    if (node >= n) return;
    float sc = rsqrtf((float)(g_z.deg_out[node] + 1));
    float4 v = h4[(size_t)node * 32 + lane];
    __nv_bfloat162 lo = __floats2bfloat162_rn(v.x * sc, v.y * sc);
    __nv_bfloat162 hi = __floats2bfloat162_rn(v.z * sc, v.w * sc);
    uint2 pk;
    pk.x = *reinterpret_cast<unsigned*>(&lo);
    pk.y = *reinterpret_cast<unsigned*>(&hi);
    ((uint2*)g_yb)[(size_t)node * 32 + lane] = pk;
    if (lane == 0) {
        int r = g_scan_tmp[node] + g_blkoff[node / SCAN_BLK];
        g_row_ptr[node] = r;
        g_cursor[node] = r;
        g_inv_in[node] = rsqrtf((float)(g_z.deg_in[node] + 1));
    }
    if (t == 0) g_row_ptr[n] = n_edges;
}

// ---------------------------------------------------------------------------
// 4) bucket fill: csr_src grouped by dst (4 edges/thread)
// ---------------------------------------------------------------------------
__global__ void fill_kernel(const int4* __restrict__ src4, const int4* __restrict__ dst4,
                            const int* __restrict__ src, const int* __restrict__ dst,
                            int n4, int n_edges) {
    int i = blockIdx.x * blockDim.x + threadIdx.x;
    if (i < n4) {
        int4 s = src4[i];
        int4 d = dst4[i];
        g_csr_src[atomicAdd(&g_cursor[d.x], 1)] = s.x;
        g_csr_src[atomicAdd(&g_cursor[d.y], 1)] = s.y;
        g_csr_src[atomicAdd(&g_cursor[d.z], 1)] = s.z;
        g_csr_src[atomicAdd(&g_cursor[d.w], 1)] = s.w;
    }
    if (blockIdx.x == gridDim.x - 1 && threadIdx.x == blockDim.x - 1) {
        for (int e = n4 * 4; e < n_edges; e++)
            g_csr_src[atomicAdd(&g_cursor[dst[e]], 1)] = src[e];
    }
}

// ---------------------------------------------------------------------------
// 5) AGG: one warp per dst node, NO smem -> full occupancy, latency hidden.
//    x[d] = (y[d] + sum_s y[s]) * wi[d], all bf16 traffic, written bf16.
// ---------------------------------------------------------------------------
__global__ __launch_bounds__(256)
void agg_kernel(int n_nodes) {
    int t = blockIdx.x * blockDim.x + threadIdx.x;
    int d = t >> 5, lane = t & 31;
    if (d >= n_nodes) return;

    const uint2* yb = (const uint2*)g_yb;
    uint2 p = __ldg(&yb[(size_t)d * 32 + lane]);   // self loop
    __nv_bfloat162 a0l = u2bf2(p.x), a0h = u2bf2(p.y);
    __nv_bfloat162 z = __float2bfloat162_rn(0.f);
    __nv_bfloat162 a1l = z, a1h = z, a2l = z, a2h = z, a3l = z, a3h = z;

    int beg = g_row_ptr[d], end = g_row_ptr[d + 1];
    for (int i0 = beg; i0 < end; i0 += 32) {
        int cnt = min(32, end - i0);
        int e = i0 + lane;
        int idx = (e < end) ? g_csr_src[e] : 0;   // coalesced
        int j = 0;
        for (; j + 8 <= cnt; j += 8) {
            int s0 = __shfl_sync(0xffffffffu, idx, j + 0);
            int s1 = __shfl_sync(0xffffffffu, idx, j + 1);
            int s2 = __shfl_sync(0xffffffffu, idx, j + 2);
            int s3 = __shfl_sync(0xffffffffu, idx, j + 3);
            int s4 = __shfl_sync(0xffffffffu, idx, j + 4);
            int s5 = __shfl_sync(0xffffffffu, idx, j + 5);
            int s6 = __shfl_sync(0xffffffffu, idx, j + 6);
            int s7 = __shfl_sync(0xffffffffu, idx, j + 7);
            uint2 q0 = __ldg(&yb[(size_t)s0 * 32 + lane]);
            uint2 q1 = __ldg(&yb[(size_t)s1 * 32 + lane]);
            uint2 q2 = __ldg(&yb[(size_t)s2 * 32 + lane]);
            uint2 q3 = __ldg(&yb[(size_t)s3 * 32 + lane]);
            uint2 q4 = __ldg(&yb[(size_t)s4 * 32 + lane]);
            uint2 q5 = __ldg(&yb[(size_t)s5 * 32 + lane]);
            uint2 q6 = __ldg(&yb[(size_t)s6 * 32 + lane]);
            uint2 q7 = __ldg(&yb[(size_t)s7 * 32 + lane]);
            a0l = __hadd2(a0l, u2bf2(q0.x)); a0h = __hadd2(a0h, u2bf2(q0.y));
            a1l = __hadd2(a1l, u2bf2(q1.x)); a1h = __hadd2(a1h, u2bf2(q1.y));
            a2l = __hadd2(a2l, u2bf2(q2.x)); a2h = __hadd2(a2h, u2bf2(q2.y));
            a3l = __hadd2(a3l, u2bf2(q3.x)); a3h = __hadd2(a3h, u2bf2(q3.y));
            a0l = __hadd2(a0l, u2bf2(q4.x)); a0h = __hadd2(a0h, u2bf2(q4.y));
            a1l = __hadd2(a1l, u2bf2(q5.x)); a1h = __hadd2(a1h, u2bf2(q5.y));
            a2l = __hadd2(a2l, u2bf2(q6.x)); a2h = __hadd2(a2h, u2bf2(q6.y));
            a3l = __hadd2(a3l, u2bf2(q7.x)); a3h = __hadd2(a3h, u2bf2(q7.y));
        }
        if (j + 4 <= cnt) {
            int s0 = __shfl_sync(0xffffffffu, idx, j + 0);
            int s1 = __shfl_sync(0xffffffffu, idx, j + 1);
            int s2 = __shfl_sync(0xffffffffu, idx, j + 2);
            int s3 = __shfl_sync(0xffffffffu, idx, j + 3);
            uint2 q0 = __ldg(&yb[(size_t)s0 * 32 + lane]);
            uint2 q1 = __ldg(&yb[(size_t)s1 * 32 + lane]);
            uint2 q2 = __ldg(&yb[(size_t)s2 * 32 + lane]);
            uint2 q3 = __ldg(&yb[(size_t)s3 * 32 + lane]);
            a0l = __hadd2(a0l, u2bf2(q0.x)); a0h = __hadd2(a0h, u2bf2(q0.y));
            a1l = __hadd2(a1l, u2bf2(q1.x)); a1h = __hadd2(a1h, u2bf2(q1.y));
            a2l = __hadd2(a2l, u2bf2(q2.x)); a2h = __hadd2(a2h, u2bf2(q2.y));
            a3l = __hadd2(a3l, u2bf2(q3.x)); a3h = __hadd2(a3h, u2bf2(q3.y));
            j += 4;
        }
        for (; j < cnt; j++) {
            int s0 = __shfl_sync(0xffffffffu, idx, j);
            uint2 q0 = __ldg(&yb[(size_t)s0 * 32 + lane]);
            a0l = __hadd2(a0l, u2bf2(q0.x)); a0h = __hadd2(a0h, u2bf2(q0.y));
        }
    }

    float wi = g_inv_in[d];
    float2 f0 = __bfloat1622float2(a0l), f1 = __bfloat1622float2(a1l);
    float2 f2 = __bfloat1622float2(a2l), f3 = __bfloat1622float2(a3l);
    float2 g0 = __bfloat1622float2(a0h), g1 = __bfloat1622float2(a1h);
    float2 g2 = __bfloat1622float2(a2h), g3 = __bfloat1622float2(a3h);
    float ox = (f0.x + f1.x + f2.x + f3.x) * wi;
    float oy = (f0.y + f1.y + f2.y + f3.y) * wi;
    float oz = (g0.x + g1.x + g2.x + g3.x) * wi;
    float ow = (g0.y + g1.y + g2.y + g3.y) * wi;
    __nv_bfloat162 lo = __floats2bfloat162_rn(ox, oy);
    __nv_bfloat162 hi = __floats2bfloat162_rn(oz, ow);
    uint2 pk;
    pk.x = *reinterpret_cast<unsigned*>(&lo);
    pk.y = *reinterpret_cast<unsigned*>(&hi);
    ((uint2*)g_xb)[(size_t)d * 32 + lane] = pk;
}

// ---------------------------------------------------------------------------
// 6) GEMV + relu + mean-sum over x (bf16, sequential reads).
//    Weights in smem (fp32); K-paired f32x2 accumulators; MB=8 nodes/warp.
// ---------------------------------------------------------------------------
__global__ __launch_bounds__(256, 2)
void gemv_kernel(const float* __restrict__ W1, const float* __restrict__ b1,
                 int n_nodes) {
    extern __shared__ float4 dyn[];
    float4* Wp   = dyn;          // [32][128] float4 = 64KB
    float4* xbuf = dyn + 4096;   // [GW][MB][32] float4 = 32KB

    for (int idx = threadIdx.x; idx < 4096; idx += blockDim.x) {
        int t2 = idx >> 7, j = idx & 127;
        Wp[idx] = make_float4(W1[(4 * t2 + 0) * 128 + j],
                              W1[(4 * t2 + 1) * 128 + j],
                              W1[(4 * t2 + 2) * 128 + j],
                              W1[(4 * t2 + 3) * 128 + j]);
    }
    __syncthreads();

    int lane = threadIdx.x & 31;
    int w    = threadIdx.x >> 5;
    int warp = blockIdx.x * GW + w;
    int nwarp = gridDim.x * GW;

    float bb[4], s[4];
#pragma unroll
    for (int c = 0; c < 4; c++) {
        bb[c] = b1[c * 32 + lane];
        s[c] = 0.f;
    }

    const ulonglong2* Wp2 = (const ulonglong2*)Wp;
    float4* xw = &xbuf[w * MB * 32];
    const ulonglong2* xb = (const ulonglong2*)xw;
    const uint2* xg = (const uint2*)g_xb;

    for (int base = warp * MB; base < n_nodes; base += nwarp * MB) {
        __syncwarp();
#pragma unroll
        for (int m = 0; m < MB; m++) {
            int n = base + m;
            float4 v = make_float4(0.f, 0.f, 0.f, 0.f);
            if (n < n_nodes) {
                uint2 p = __ldg(&xg[(size_t)n * 32 + lane]);
                float2 lo = __bfloat1622float2(u2bf2(p.x));
                float2 hi = __bfloat1622float2(u2bf2(p.y));
                v = make_float4(lo.x, lo.y, hi.x, hi.y);
            }
            xw[m * 32 + lane] = v;
        }
        __syncwarp();

        unsigned long long acc[MB][4];
#pragma unroll
        for (int m = 0; m < MB; m++)
#pragma unroll
            for (int c = 0; c < 4; c++) acc[m][c] = 0ull;

#pragma unroll 2
        for (int t2 = 0; t2 < 32; t2++) {
            ulonglong2 wv[4];
#pragma unroll
            for (int c = 0; c < 4; c++)
                wv[c] = Wp2[t2 * 128 + c * 32 + lane];
#pragma unroll
            for (int m = 0; m < MB; m++) {
                ulonglong2 xm = xb[m * 32 + t2];   // broadcast
#pragma unroll
                for (int c = 0; c < 4; c++) {
                    asm("fma.rn.f32x2 %0, %1, %2, %0;"
                        : "+l"(acc[m][c]) : "l"(wv[c].x), "l"(xm.x));
                    asm("fma.rn.f32x2 %0, %1, %2, %0;"
                        : "+l"(acc[m][c]) : "l"(wv[c].y), "l"(xm.y));
                }
            }
        }

#pragma unroll
        for (int m = 0; m < MB; m++) {
            if (base + m >= n_nodes) break;
#pragma unroll
            for (int c = 0; c < 4; c++) {
                unsigned lo, hi;
                asm("mov.b64 {%0, %1}, %2;" : "=r"(lo), "=r"(hi) : "l"(acc[m][c]));
                float y = __uint_as_float(lo) + __uint_as_float(hi) + bb[c];
                s[c] += fmaxf(y, 0.f);
            }
        }
    }

#pragma unroll
    for (int c = 0; c < 4; c++)
        atomicAdd(&g_z.hsum[c * 32 + lane], s[c]);
}

// ---------------------------------------------------------------------------
// 7) classifier heads, split-K over 4 warps
// ---------------------------------------------------------------------------
__global__ void head_kernel(const float* __restrict__ Wc1, const float* __restrict__ bc1,
                            const float* __restrict__ Wc2, const float* __restrict__ bc2,
                            float* __restrict__ out, float inv_n) {
    __shared__ float red[128];
    int t = threadIdx.x;          // 0..127
    int o = t & 31;               // output index
    int part = t >> 5;            // k-quarter
    const float* Wc = (o < 16) ? Wc1 : Wc2;
    int c = o & 15;
    float acc = 0.f;
#pragma unroll 8
    for (int k = part * 32; k < part * 32 + 32; k++)
        acc += g_z.hsum[k] * Wc[k * 16 + c];
    red[t] = acc;
    __syncthreads();
    if (t < 32) {
        const float* bc = (t < 16) ? bc1 : bc2;
        float v = red[t] + red[t + 32] + red[t + 64] + red[t + 96];
        out[t] = v * inv_n + bc[c];
    }
}

// ---------------------------------------------------------------------------
extern "C" void kernel_launch(void* const* d_in, const int* in_sizes, int n_in,
                              void* d_out, int out_size) {
    const float* h   = (const float*)d_in[0];
    const int*   src = (const int*)d_in[1];
    const int*   dst = (const int*)d_in[2];
    const float* W1  = (const float*)d_in[3];
    const float* b1  = (const float*)d_in[4];
    const float* Wc1 = (const float*)d_in[5];
    const float* bc1 = (const float*)d_in[6];
    const float* Wc2 = (const float*)d_in[7];
    const float* bc2 = (const float*)d_in[8];

    int n_nodes = in_sizes[0] / DIM;
    int n_edges = in_sizes[1];
    int n4 = n_edges / 4;

    static bool s_init = false;
    if (!s_init) {
        cudaFuncSetAttribute(gemv_kernel,
                             cudaFuncAttributeMaxDynamicSharedMemorySize, 98304);
        s_init = true;
    }

    void* z_p = nullptr;
    cudaGetSymbolAddress(&z_p, g_z);
    cudaMemsetAsync(z_p, 0, sizeof(g_z));   // deg_out + deg_in + hsum, one call

    deg_kernel<<<(n4 + 255) / 256, 256>>>((const int4*)src, (const int4*)dst,
                                          src, dst, n4, n_edges);

    int nb = (n_nodes + SCAN_BLK - 1) / SCAN_BLK;
    scan1_kernel<<<nb, SCAN_BLK>>>(n_nodes);
    scan2_kernel<<<1, 256>>>(nb);

    long long nthr = (long long)n_nodes * 32;
    int nblk = (int)((nthr + 255) / 256);
    scan3p_kernel<<<nblk, 256>>>((const float4*)h, n_nodes, n_edges);

    fill_kernel<<<(n4 + 255) / 256, 256>>>((const int4*)src, (const int4*)dst,
                                           src, dst, n4, n_edges);

    agg_kernel<<<nblk, 256>>>(n_nodes);

    gemv_kernel<<<296, 256, 98304>>>(W1, b1, n_nodes);

    head_kernel<<<1, 128>>>(Wc1, bc1, Wc2, bc2, (float*)d_out, 1.0f / (float)n_nodes);
}

// round 11
// speedup vs baseline: 1.6758x; 1.3869x over previous
#include <cuda_runtime.h>
#include <cuda_bf16.h>
#include <cstdint>

#define DIM 128
#define NMAX 100000
#define EMAX 1600000
#define SCAN_BLK 1024

// Scratch (device globals: allocation-free per harness rules)
__device__ __nv_bfloat16 g_yb[(size_t)NMAX * DIM];  // prescaled h * inv_out, bf16
__device__ __nv_bfloat16 g_xb[(size_t)NMAX * DIM];  // aggregated conv input, bf16
__device__ struct { int deg_out[NMAX]; int deg_in[NMAX]; float hsum[DIM]; } g_z;
__device__ float g_inv_in[NMAX];
__device__ int   g_row_ptr[NMAX + 1];
__device__ int   g_cursor[NMAX];
__device__ int   g_csr_src[EMAX];
__device__ int   g_blksum[256];
__device__ int   g_blkoff[256];
__device__ int   g_scan_tmp[NMAX];

__device__ __forceinline__ __nv_bfloat162 u2bf2(unsigned u) {
    return *reinterpret_cast<__nv_bfloat162*>(&u);
}

// ---------------------------------------------------------------------------
// 1) degree counting, vectorized 4 edges/thread
// ---------------------------------------------------------------------------
__global__ void deg_kernel(const int4* __restrict__ src4, const int4* __restrict__ dst4,
                           const int* __restrict__ src, const int* __restrict__ dst,
                           int n4, int n_edges) {
    int i = blockIdx.x * blockDim.x + threadIdx.x;
    if (i < n4) {
        int4 s = src4[i];
        atomicAdd(&g_z.deg_out[s.x], 1); atomicAdd(&g_z.deg_out[s.y], 1);
        atomicAdd(&g_z.deg_out[s.z], 1); atomicAdd(&g_z.deg_out[s.w], 1);
        int4 d = dst4[i];
        atomicAdd(&g_z.deg_in[d.x], 1); atomicAdd(&g_z.deg_in[d.y], 1);
        atomicAdd(&g_z.deg_in[d.z], 1); atomicAdd(&g_z.deg_in[d.w], 1);
    }
    if (blockIdx.x == gridDim.x - 1 && threadIdx.x == blockDim.x - 1) {
        for (int e = n4 * 4; e < n_edges; e++) {
            atomicAdd(&g_z.deg_out[src[e]], 1);
            atomicAdd(&g_z.deg_in[dst[e]], 1);
        }
    }
}

// ---------------------------------------------------------------------------
// 2) exclusive scan of deg_in -> row_ptr (2-level scan)
// ---------------------------------------------------------------------------
__global__ void scan1_kernel(int n) {
    __shared__ int sm[SCAN_BLK];
    int i = blockIdx.x * SCAN_BLK + threadIdx.x;
    int v = (i < n) ? g_z.deg_in[i] : 0;
    sm[threadIdx.x] = v;
    __syncthreads();
#pragma unroll
    for (int off = 1; off < SCAN_BLK; off <<= 1) {
        int t = (threadIdx.x >= off) ? sm[threadIdx.x - off] : 0;
        __syncthreads();
        sm[threadIdx.x] += t;
        __syncthreads();
    }
    if (i < n) g_scan_tmp[i] = sm[threadIdx.x] - v;   // exclusive
    if (threadIdx.x == SCAN_BLK - 1) g_blksum[blockIdx.x] = sm[SCAN_BLK - 1];
}

__global__ void scan2_kernel(int nb) {
    __shared__ int sm[256];
    int t = threadIdx.x;
    int v = (t < nb) ? g_blksum[t] : 0;
    sm[t] = v;
    __syncthreads();
#pragma unroll
    for (int off = 1; off < 256; off <<= 1) {
        int u = (t >= off) ? sm[t - off] : 0;
        __syncthreads();
        sm[t] += u;
        __syncthreads();
    }
    if (t < nb) g_blkoff[t] = sm[t] - v;   // exclusive
}

// ---------------------------------------------------------------------------
// 3) merged: row_ptr/cursor/inv_in finalize + bf16 prescale of features.
// ---------------------------------------------------------------------------
__global__ void scan3p_kernel(const float4* __restrict__ h4, int n, int n_edges) {
    int t = blockIdx.x * blockDim.x + threadIdx.x;
    int node = t >> 5, lane = t & 31;
    if (node >= n) return;
    float sc = rsqrtf((float)(g_z.deg_out[node] + 1));
    float4 v = h4[(size_t)node * 32 + lane];
    __nv_bfloat162 lo = __floats2bfloat162_rn(v.x * sc, v.y * sc);
    __nv_bfloat162 hi = __floats2bfloat162_rn(v.z * sc, v.w * sc);
    uint2 pk;
    pk.x = *reinterpret_cast<unsigned*>(&lo);
    pk.y = *reinterpret_cast<unsigned*>(&hi);
    ((uint2*)g_yb)[(size_t)node * 32 + lane] = pk;
    if (lane == 0) {
        int r = g_scan_tmp[node] + g_blkoff[node / SCAN_BLK];
        g_row_ptr[node] = r;
        g_cursor[node] = r;
        g_inv_in[node] = rsqrtf((float)(g_z.deg_in[node] + 1));
    }
    if (t == 0) g_row_ptr[n] = n_edges;
}

// ---------------------------------------------------------------------------
// 4) bucket fill: csr_src grouped by dst (4 edges/thread)
// ---------------------------------------------------------------------------
__global__ void fill_kernel(const int4* __restrict__ src4, const int4* __restrict__ dst4,
                            const int* __restrict__ src, const int* __restrict__ dst,
                            int n4, int n_edges) {
    int i = blockIdx.x * blockDim.x + threadIdx.x;
    if (i < n4) {
        int4 s = src4[i];
        int4 d = dst4[i];
        g_csr_src[atomicAdd(&g_cursor[d.x], 1)] = s.x;
        g_csr_src[atomicAdd(&g_cursor[d.y], 1)] = s.y;
        g_csr_src[atomicAdd(&g_cursor[d.z], 1)] = s.z;
        g_csr_src[atomicAdd(&g_cursor[d.w], 1)] = s.w;
    }
    if (blockIdx.x == gridDim.x - 1 && threadIdx.x == blockDim.x - 1) {
        for (int e = n4 * 4; e < n_edges; e++)
            g_csr_src[atomicAdd(&g_cursor[dst[e]], 1)] = src[e];
    }
}

// ---------------------------------------------------------------------------
// 5) AGG: one warp per dst node, NO smem -> full occupancy, latency hidden.
// ---------------------------------------------------------------------------
__global__ __launch_bounds__(256)
void agg_kernel(int n_nodes) {
    int t = blockIdx.x * blockDim.x + threadIdx.x;
    int d = t >> 5, lane = t & 31;
    if (d >= n_nodes) return;

    const uint2* yb = (const uint2*)g_yb;
    uint2 p = __ldg(&yb[(size_t)d * 32 + lane]);   // self loop
    __nv_bfloat162 a0l = u2bf2(p.x), a0h = u2bf2(p.y);
    __nv_bfloat162 z = __float2bfloat162_rn(0.f);
    __nv_bfloat162 a1l = z, a1h = z, a2l = z, a2h = z, a3l = z, a3h = z;

    int beg = g_row_ptr[d], end = g_row_ptr[d + 1];
    for (int i0 = beg; i0 < end; i0 += 32) {
        int cnt = min(32, end - i0);
        int e = i0 + lane;
        int idx = (e < end) ? g_csr_src[e] : 0;   // coalesced
        int j = 0;
        for (; j + 8 <= cnt; j += 8) {
            int s0 = __shfl_sync(0xffffffffu, idx, j + 0);
            int s1 = __shfl_sync(0xffffffffu, idx, j + 1);
            int s2 = __shfl_sync(0xffffffffu, idx, j + 2);
            int s3 = __shfl_sync(0xffffffffu, idx, j + 3);
            int s4 = __shfl_sync(0xffffffffu, idx, j + 4);
            int s5 = __shfl_sync(0xffffffffu, idx, j + 5);
            int s6 = __shfl_sync(0xffffffffu, idx, j + 6);
            int s7 = __shfl_sync(0xffffffffu, idx, j + 7);
            uint2 q0 = __ldg(&yb[(size_t)s0 * 32 + lane]);
            uint2 q1 = __ldg(&yb[(size_t)s1 * 32 + lane]);
            uint2 q2 = __ldg(&yb[(size_t)s2 * 32 + lane]);
            uint2 q3 = __ldg(&yb[(size_t)s3 * 32 + lane]);
            uint2 q4 = __ldg(&yb[(size_t)s4 * 32 + lane]);
            uint2 q5 = __ldg(&yb[(size_t)s5 * 32 + lane]);
            uint2 q6 = __ldg(&yb[(size_t)s6 * 32 + lane]);
            uint2 q7 = __ldg(&yb[(size_t)s7 * 32 + lane]);
            a0l = __hadd2(a0l, u2bf2(q0.x)); a0h = __hadd2(a0h, u2bf2(q0.y));
            a1l = __hadd2(a1l, u2bf2(q1.x)); a1h = __hadd2(a1h, u2bf2(q1.y));
            a2l = __hadd2(a2l, u2bf2(q2.x)); a2h = __hadd2(a2h, u2bf2(q2.y));
            a3l = __hadd2(a3l, u2bf2(q3.x)); a3h = __hadd2(a3h, u2bf2(q3.y));
            a0l = __hadd2(a0l, u2bf2(q4.x)); a0h = __hadd2(a0h, u2bf2(q4.y));
            a1l = __hadd2(a1l, u2bf2(q5.x)); a1h = __hadd2(a1h, u2bf2(q5.y));
            a2l = __hadd2(a2l, u2bf2(q6.x)); a2h = __hadd2(a2h, u2bf2(q6.y));
            a3l = __hadd2(a3l, u2bf2(q7.x)); a3h = __hadd2(a3h, u2bf2(q7.y));
        }
        if (j + 4 <= cnt) {
            int s0 = __shfl_sync(0xffffffffu, idx, j + 0);
            int s1 = __shfl_sync(0xffffffffu, idx, j + 1);
            int s2 = __shfl_sync(0xffffffffu, idx, j + 2);
            int s3 = __shfl_sync(0xffffffffu, idx, j + 3);
            uint2 q0 = __ldg(&yb[(size_t)s0 * 32 + lane]);
            uint2 q1 = __ldg(&yb[(size_t)s1 * 32 + lane]);
            uint2 q2 = __ldg(&yb[(size_t)s2 * 32 + lane]);
            uint2 q3 = __ldg(&yb[(size_t)s3 * 32 + lane]);
            a0l = __hadd2(a0l, u2bf2(q0.x)); a0h = __hadd2(a0h, u2bf2(q0.y));
            a1l = __hadd2(a1l, u2bf2(q1.x)); a1h = __hadd2(a1h, u2bf2(q1.y));
            a2l = __hadd2(a2l, u2bf2(q2.x)); a2h = __hadd2(a2h, u2bf2(q2.y));
            a3l = __hadd2(a3l, u2bf2(q3.x)); a3h = __hadd2(a3h, u2bf2(q3.y));
            j += 4;
        }
        for (; j < cnt; j++) {
            int s0 = __shfl_sync(0xffffffffu, idx, j);
            uint2 q0 = __ldg(&yb[(size_t)s0 * 32 + lane]);
            a0l = __hadd2(a0l, u2bf2(q0.x)); a0h = __hadd2(a0h, u2bf2(q0.y));
        }
    }

    float wi = g_inv_in[d];
    float2 f0 = __bfloat1622float2(a0l), f1 = __bfloat1622float2(a1l);
    float2 f2 = __bfloat1622float2(a2l), f3 = __bfloat1622float2(a3l);
    float2 g0 = __bfloat1622float2(a0h), g1 = __bfloat1622float2(a1h);
    float2 g2 = __bfloat1622float2(a2h), g3 = __bfloat1622float2(a3h);
    float ox = (f0.x + f1.x + f2.x + f3.x) * wi;
    float oy = (f0.y + f1.y + f2.y + f3.y) * wi;
    float oz = (g0.x + g1.x + g2.x + g3.x) * wi;
    float ow = (g0.y + g1.y + g2.y + g3.y) * wi;
    __nv_bfloat162 lo = __floats2bfloat162_rn(ox, oy);
    __nv_bfloat162 hi = __floats2bfloat162_rn(oz, ow);
    uint2 pk;
    pk.x = *reinterpret_cast<unsigned*>(&lo);
    pk.y = *reinterpret_cast<unsigned*>(&hi);
    ((uint2*)g_xb)[(size_t)d * 32 + lane] = pk;
}

// ---------------------------------------------------------------------------
// 6) GEMV via tensor cores: y = relu(x @ (W_hi + W_lo) + b), column-summed.
//    mma.sync.m16n8k16 bf16, fp32 accum. Warp w owns output cols [16w,16w+16)
//    (2 n-tiles), W fragments resident in registers (canonical B mapping).
//    Block stages 64-node x chunks in smem (row stride 136 bf16 -> bank-clean).
// ---------------------------------------------------------------------------
#define CHUNK 64
#define XSTR 136   // bf16 elements per padded smem row (272B)

__global__ __launch_bounds__(256)
void gemv_mma_kernel(const float* __restrict__ W1, const float* __restrict__ b1,
                     int n_nodes) {
    __shared__ __nv_bfloat16 xs[CHUNK * XSTR];   // 17408 B

    int lane = threadIdx.x & 31;
    int w    = threadIdx.x >> 5;
    int m4   = lane & 3;     // l%4
    int q    = lane >> 2;    // l/4

    // ---- build W fragments (hi + lo split), canonical m16n8k16 B layout ----
    unsigned bhi[8][2][2], blo[8][2][2];
#pragma unroll
    for (int kk = 0; kk < 8; kk++) {
#pragma unroll
        for (int t = 0; t < 2; t++) {
            int col = w * 16 + t * 8 + q;
            int k0 = kk * 16 + 2 * m4;
#pragma unroll
            for (int r = 0; r < 2; r++) {
                int ka = k0 + r * 8, kb = ka + 1;
                float wa = W1[ka * DIM + col];
                float wb = W1[kb * DIM + col];
                __nv_bfloat16 ha = __float2bfloat16(wa);
                __nv_bfloat16 hb = __float2bfloat16(wb);
                __nv_bfloat16 la = __float2bfloat16(wa - __bfloat162float(ha));
                __nv_bfloat16 lb = __float2bfloat16(wb - __bfloat162float(hb));
                unsigned ua = *reinterpret_cast<unsigned short*>(&ha);
                unsigned ub = *reinterpret_cast<unsigned short*>(&hb);
                bhi[kk][t][r] = ua | (ub << 16);
                ua = *reinterpret_cast<unsigned short*>(&la);
                ub = *reinterpret_cast<unsigned short*>(&lb);
                blo[kk][t][r] = ua | (ub << 16);
            }
        }
    }

    float be[2], bo[2];
#pragma unroll
    for (int t = 0; t < 2; t++) {
        be[t] = b1[w * 16 + t * 8 + 2 * m4];
        bo[t] = b1[w * 16 + t * 8 + 2 * m4 + 1];
    }

    float cs[2][2];   // [ntile][even/odd] column partial sums
    cs[0][0] = cs[0][1] = cs[1][0] = cs[1][1] = 0.f;

    const uint2* xg = (const uint2*)g_xb;
    int nchunk = (n_nodes + CHUNK - 1) / CHUNK;

    for (int ch = blockIdx.x; ch < nchunk; ch += gridDim.x) {
        int base = ch * CHUNK;
        // ---- stage CHUNK node rows into padded smem ----
        __syncthreads();
        for (int i = threadIdx.x; i < CHUNK * 32; i += blockDim.x) {
            int row = i >> 5, c8 = i & 31;   // c8: which uint2 (4 bf16) of row
            int n = base + row;
            uint2 v = make_uint2(0u, 0u);
            if (n < n_nodes) v = __ldg(&xg[(size_t)n * 32 + c8]);
            unsigned* dstp = reinterpret_cast<unsigned*>(&xs[row * XSTR + c8 * 4]);
            dstp[0] = v.x; dstp[1] = v.y;
        }
        __syncthreads();

#pragma unroll
        for (int mb = 0; mb < CHUNK / 16; mb++) {
            int rbase = mb * 16;
            float c[2][4];
#pragma unroll
            for (int t = 0; t < 2; t++)
#pragma unroll
                for (int r = 0; r < 4; r++) c[t][r] = 0.f;

#pragma unroll
            for (int kk = 0; kk < 8; kk++) {
                // A fragments: canonical m16n8k16 layout via direct LDS.32
                const unsigned* xrow0 = reinterpret_cast<const unsigned*>(
                    &xs[(rbase + q) * XSTR + kk * 16 + 2 * m4]);
                const unsigned* xrow1 = reinterpret_cast<const unsigned*>(
                    &xs[(rbase + q + 8) * XSTR + kk * 16 + 2 * m4]);
                unsigned a0 = xrow0[0];
                unsigned a1 = xrow1[0];
                unsigned a2 = xrow0[4];   // +8 bf16 = +16B = +4 words
                unsigned a3 = xrow1[4];
#pragma unroll
                for (int t = 0; t < 2; t++) {
                    asm volatile(
                        "mma.sync.aligned.m16n8k16.row.col.f32.bf16.bf16.f32 "
                        "{%0,%1,%2,%3}, {%4,%5,%6,%7}, {%8,%9}, {%0,%1,%2,%3};"
                        : "+f"(c[t][0]), "+f"(c[t][1]), "+f"(c[t][2]), "+f"(c[t][3])
                        : "r"(a0), "r"(a1), "r"(a2), "r"(a3),
                          "r"(bhi[kk][t][0]), "r"(bhi[kk][t][1]));
                    asm volatile(
                        "mma.sync.aligned.m16n8k16.row.col.f32.bf16.bf16.f32 "
                        "{%0,%1,%2,%3}, {%4,%5,%6,%7}, {%8,%9}, {%0,%1,%2,%3};"
                        : "+f"(c[t][0]), "+f"(c[t][1]), "+f"(c[t][2]), "+f"(c[t][3])
                        : "r"(a0), "r"(a1), "r"(a2), "r"(a3),
                          "r"(blo[kk][t][0]), "r"(blo[kk][t][1]));
                }
            }

            // bias + relu + masked accumulate (rows q and q+8 of this batch)
            bool v0 = (base + rbase + q) < n_nodes;
            bool v1 = (base + rbase + q + 8) < n_nodes;
#pragma unroll
            for (int t = 0; t < 2; t++) {
                if (v0) {
                    cs[t][0] += fmaxf(c[t][0] + be[t], 0.f);
                    cs[t][1] += fmaxf(c[t][1] + bo[t], 0.f);
                }
                if (v1) {
                    cs[t][2 - 2] += 0.f;  // keep structure; real adds below
                }
                if (v1) {
                    cs[t][0] += fmaxf(c[t][2] + be[t], 0.f);
                    cs[t][1] += fmaxf(c[t][3] + bo[t], 0.f);
                }
            }
        }
    }

    // reduce over the 8 row-groups (lanes sharing l%4) and commit
#pragma unroll
    for (int t = 0; t < 2; t++) {
#pragma unroll
        for (int e = 0; e < 2; e++) {
            float v = cs[t][e];
            v += __shfl_xor_sync(0xffffffffu, v, 16);
            v += __shfl_xor_sync(0xffffffffu, v, 8);
            v += __shfl_xor_sync(0xffffffffu, v, 4);
            if (q == 0)
                atomicAdd(&g_z.hsum[w * 16 + t * 8 + 2 * m4 + e], v);
        }
    }
}

// ---------------------------------------------------------------------------
// 7) classifier heads, split-K over 4 warps
// ---------------------------------------------------------------------------
__global__ void head_kernel(const float* __restrict__ Wc1, const float* __restrict__ bc1,
                            const float* __restrict__ Wc2, const float* __restrict__ bc2,
                            float* __restrict__ out, float inv_n) {
    __shared__ float red[128];
    int t = threadIdx.x;
    int o = t & 31;
    int part = t >> 5;
    const float* Wc = (o < 16) ? Wc1 : Wc2;
    int c = o & 15;
    float acc = 0.f;
#pragma unroll 8
    for (int k = part * 32; k < part * 32 + 32; k++)
        acc += g_z.hsum[k] * Wc[k * 16 + c];
    red[t] = acc;
    __syncthreads();
    if (t < 32) {
        const float* bc = (t < 16) ? bc1 : bc2;
        float v = red[t] + red[t + 32] + red[t + 64] + red[t + 96];
        out[t] = v * inv_n + bc[c];
    }
}

// ---------------------------------------------------------------------------
extern "C" void kernel_launch(void* const* d_in, const int* in_sizes, int n_in,
                              void* d_out, int out_size) {
    const float* h   = (const float*)d_in[0];
    const int*   src = (const int*)d_in[1];
    const int*   dst = (const int*)d_in[2];
    const float* W1  = (const float*)d_in[3];
    const float* b1  = (const float*)d_in[4];
    const float* Wc1 = (const float*)d_in[5];
    const float* bc1 = (const float*)d_in[6];
    const float* Wc2 = (const float*)d_in[7];
    const float* bc2 = (const float*)d_in[8];

    int n_nodes = in_sizes[0] / DIM;
    int n_edges = in_sizes[1];
    int n4 = n_edges / 4;

    void* z_p = nullptr;
    cudaGetSymbolAddress(&z_p, g_z);
    cudaMemsetAsync(z_p, 0, sizeof(g_z));

    deg_kernel<<<(n4 + 255) / 256, 256>>>((const int4*)src, (const int4*)dst,
                                          src, dst, n4, n_edges);

    int nb = (n_nodes + SCAN_BLK - 1) / SCAN_BLK;
    scan1_kernel<<<nb, SCAN_BLK>>>(n_nodes);
    scan2_kernel<<<1, 256>>>(nb);

    long long nthr = (long long)n_nodes * 32;
    int nblk = (int)((nthr + 255) / 256);
    scan3p_kernel<<<nblk, 256>>>((const float4*)h, n_nodes, n_edges);

    fill_kernel<<<(n4 + 255) / 256, 256>>>((const int4*)src, (const int4*)dst,
                                           src, dst, n4, n_edges);

    agg_kernel<<<nblk, 256>>>(n_nodes);

    gemv_mma_kernel<<<296, 256>>>(W1, b1, n_nodes);

    head_kernel<<<1, 128>>>(Wc1, bc1, Wc2, bc2, (float*)d_out, 1.0f / (float)n_nodes);
}

// round 12
// speedup vs baseline: 1.7059x; 1.0179x over previous
#include <cuda_runtime.h>
#include <cuda_bf16.h>
#include <cstdint>

#define DIM 128
#define NMAX 100000
#define EMAX 1600000
#define SCAN_BLK 1024

// Scratch (device globals: allocation-free per harness rules)
__device__ __nv_bfloat16 g_yb[(size_t)NMAX * DIM];  // prescaled h * inv_out, bf16
__device__ __nv_bfloat16 g_xb[(size_t)NMAX * DIM];  // aggregated conv input, bf16
__device__ struct { int deg_out[NMAX]; int deg_in[NMAX]; float hsum[DIM]; } g_z;
__device__ float g_inv_in[NMAX];
__device__ int   g_row_ptr[NMAX + 1];
__device__ int   g_cursor[NMAX];
__device__ int   g_csr_src[EMAX];
__device__ int   g_blksum[256];
__device__ int   g_blkoff[256];
__device__ int   g_scan_tmp[NMAX];

__device__ __forceinline__ __nv_bfloat162 u2bf2(unsigned u) {
    return *reinterpret_cast<__nv_bfloat162*>(&u);
}

// ---------------------------------------------------------------------------
// 1) degree counting, vectorized 4 edges/thread
// ---------------------------------------------------------------------------
__global__ void deg_kernel(const int4* __restrict__ src4, const int4* __restrict__ dst4,
                           const int* __restrict__ src, const int* __restrict__ dst,
                           int n4, int n_edges) {
    int i = blockIdx.x * blockDim.x + threadIdx.x;
    if (i < n4) {
        int4 s = src4[i];
        atomicAdd(&g_z.deg_out[s.x], 1); atomicAdd(&g_z.deg_out[s.y], 1);
        atomicAdd(&g_z.deg_out[s.z], 1); atomicAdd(&g_z.deg_out[s.w], 1);
        int4 d = dst4[i];
        atomicAdd(&g_z.deg_in[d.x], 1); atomicAdd(&g_z.deg_in[d.y], 1);
        atomicAdd(&g_z.deg_in[d.z], 1); atomicAdd(&g_z.deg_in[d.w], 1);
    }
    if (blockIdx.x == gridDim.x - 1 && threadIdx.x == blockDim.x - 1) {
        for (int e = n4 * 4; e < n_edges; e++) {
            atomicAdd(&g_z.deg_out[src[e]], 1);
            atomicAdd(&g_z.deg_in[dst[e]], 1);
        }
    }
}

// ---------------------------------------------------------------------------
// 2) exclusive scan of deg_in -> row_ptr (2-level scan)
// ---------------------------------------------------------------------------
__global__ void scan1_kernel(int n) {
    __shared__ int sm[SCAN_BLK];
    int i = blockIdx.x * SCAN_BLK + threadIdx.x;
    int v = (i < n) ? g_z.deg_in[i] : 0;
    sm[threadIdx.x] = v;
    __syncthreads();
#pragma unroll
    for (int off = 1; off < SCAN_BLK; off <<= 1) {
        int t = (threadIdx.x >= off) ? sm[threadIdx.x - off] : 0;
        __syncthreads();
        sm[threadIdx.x] += t;
        __syncthreads();
    }
    if (i < n) g_scan_tmp[i] = sm[threadIdx.x] - v;   // exclusive
    if (threadIdx.x == SCAN_BLK - 1) g_blksum[blockIdx.x] = sm[SCAN_BLK - 1];
}

__global__ void scan2_kernel(int nb) {
    __shared__ int sm[256];
    int t = threadIdx.x;
    int v = (t < nb) ? g_blksum[t] : 0;
    sm[t] = v;
    __syncthreads();
#pragma unroll
    for (int off = 1; off < 256; off <<= 1) {
        int u = (t >= off) ? sm[t - off] : 0;
        __syncthreads();
        sm[t] += u;
        __syncthreads();
    }
    if (t < nb) g_blkoff[t] = sm[t] - v;   // exclusive
}

// ---------------------------------------------------------------------------
// 3a) finalize: row_ptr / cursor / inv_in (one thread per node)
// ---------------------------------------------------------------------------
__global__ void scan3_kernel(int n, int n_edges) {
    int i = blockIdx.x * blockDim.x + threadIdx.x;
    if (i < n) {
        int r = g_scan_tmp[i] + g_blkoff[i / SCAN_BLK];
        g_row_ptr[i] = r;
        g_cursor[i] = r;
        g_inv_in[i] = rsqrtf((float)(g_z.deg_in[i] + 1));
    }
    if (i == 0) g_row_ptr[n] = n_edges;
}

// ---------------------------------------------------------------------------
// 3b) bf16 prescale (side stream, overlaps scan/fill): y = h * inv_out.
//     One warp per node; rsqrt computed ONCE per node (lane 0 + shfl) —
//     removes the MUFU throughput wall (was 1 rsqrt/element).
// ---------------------------------------------------------------------------
__global__ void prescale_kernel(const float4* __restrict__ h4, int n) {
    int t = blockIdx.x * blockDim.x + threadIdx.x;
    int node = t >> 5, lane = t & 31;
    if (node >= n) return;
    float sc = 0.f;
    if (lane == 0) sc = rsqrtf((float)(g_z.deg_out[node] + 1));
    sc = __shfl_sync(0xffffffffu, sc, 0);
    float4 v = h4[(size_t)node * 32 + lane];
    __nv_bfloat162 lo = __floats2bfloat162_rn(v.x * sc, v.y * sc);
    __nv_bfloat162 hi = __floats2bfloat162_rn(v.z * sc, v.w * sc);
    uint2 pk;
    pk.x = *reinterpret_cast<unsigned*>(&lo);
    pk.y = *reinterpret_cast<unsigned*>(&hi);
    ((uint2*)g_yb)[(size_t)node * 32 + lane] = pk;
}

// ---------------------------------------------------------------------------
// 4) bucket fill: csr_src grouped by dst (4 edges/thread)
// ---------------------------------------------------------------------------
__global__ void fill_kernel(const int4* __restrict__ src4, const int4* __restrict__ dst4,
                            const int* __restrict__ src, const int* __restrict__ dst,
                            int n4, int n_edges) {
    int i = blockIdx.x * blockDim.x + threadIdx.x;
    if (i < n4) {
        int4 s = src4[i];
        int4 d = dst4[i];
        g_csr_src[atomicAdd(&g_cursor[d.x], 1)] = s.x;
        g_csr_src[atomicAdd(&g_cursor[d.y], 1)] = s.y;
        g_csr_src[atomicAdd(&g_cursor[d.z], 1)] = s.z;
        g_csr_src[atomicAdd(&g_cursor[d.w], 1)] = s.w;
    }
    if (blockIdx.x == gridDim.x - 1 && threadIdx.x == blockDim.x - 1) {
        for (int e = n4 * 4; e < n_edges; e++)
            g_csr_src[atomicAdd(&g_cursor[dst[e]], 1)] = src[e];
    }
}

// ---------------------------------------------------------------------------
// 5) AGG: one warp per dst node, NO smem -> full occupancy, latency hidden.
// ---------------------------------------------------------------------------
__global__ __launch_bounds__(256)
void agg_kernel(int n_nodes) {
    int t = blockIdx.x * blockDim.x + threadIdx.x;
    int d = t >> 5, lane = t & 31;
    if (d >= n_nodes) return;

    const uint2* yb = (const uint2*)g_yb;
    uint2 p = __ldg(&yb[(size_t)d * 32 + lane]);   // self loop
    __nv_bfloat162 a0l = u2bf2(p.x), a0h = u2bf2(p.y);
    __nv_bfloat162 z = __float2bfloat162_rn(0.f);
    __nv_bfloat162 a1l = z, a1h = z, a2l = z, a2h = z, a3l = z, a3h = z;

    int beg = g_row_ptr[d], end = g_row_ptr[d + 1];
    for (int i0 = beg; i0 < end; i0 += 32) {
        int cnt = min(32, end - i0);
        int e = i0 + lane;
        int idx = (e < end) ? g_csr_src[e] : 0;   // coalesced
        int j = 0;
        for (; j + 8 <= cnt; j += 8) {
            int s0 = __shfl_sync(0xffffffffu, idx, j + 0);
            int s1 = __shfl_sync(0xffffffffu, idx, j + 1);
            int s2 = __shfl_sync(0xffffffffu, idx, j + 2);
            int s3 = __shfl_sync(0xffffffffu, idx, j + 3);
            int s4 = __shfl_sync(0xffffffffu, idx, j + 4);
            int s5 = __shfl_sync(0xffffffffu, idx, j + 5);
            int s6 = __shfl_sync(0xffffffffu, idx, j + 6);
            int s7 = __shfl_sync(0xffffffffu, idx, j + 7);
            uint2 q0 = __ldg(&yb[(size_t)s0 * 32 + lane]);
            uint2 q1 = __ldg(&yb[(size_t)s1 * 32 + lane]);
            uint2 q2 = __ldg(&yb[(size_t)s2 * 32 + lane]);
            uint2 q3 = __ldg(&yb[(size_t)s3 * 32 + lane]);
            uint2 q4 = __ldg(&yb[(size_t)s4 * 32 + lane]);
            uint2 q5 = __ldg(&yb[(size_t)s5 * 32 + lane]);
            uint2 q6 = __ldg(&yb[(size_t)s6 * 32 + lane]);
            uint2 q7 = __ldg(&yb[(size_t)s7 * 32 + lane]);
            a0l = __hadd2(a0l, u2bf2(q0.x)); a0h = __hadd2(a0h, u2bf2(q0.y));
            a1l = __hadd2(a1l, u2bf2(q1.x)); a1h = __hadd2(a1h, u2bf2(q1.y));
            a2l = __hadd2(a2l, u2bf2(q2.x)); a2h = __hadd2(a2h, u2bf2(q2.y));
            a3l = __hadd2(a3l, u2bf2(q3.x)); a3h = __hadd2(a3h, u2bf2(q3.y));
            a0l = __hadd2(a0l, u2bf2(q4.x)); a0h = __hadd2(a0h, u2bf2(q4.y));
            a1l = __hadd2(a1l, u2bf2(q5.x)); a1h = __hadd2(a1h, u2bf2(q5.y));
            a2l = __hadd2(a2l, u2bf2(q6.x)); a2h = __hadd2(a2h, u2bf2(q6.y));
            a3l = __hadd2(a3l, u2bf2(q7.x)); a3h = __hadd2(a3h, u2bf2(q7.y));
        }
        if (j + 4 <= cnt) {
            int s0 = __shfl_sync(0xffffffffu, idx, j + 0);
            int s1 = __shfl_sync(0xffffffffu, idx, j + 1);
            int s2 = __shfl_sync(0xffffffffu, idx, j + 2);
            int s3 = __shfl_sync(0xffffffffu, idx, j + 3);
            uint2 q0 = __ldg(&yb[(size_t)s0 * 32 + lane]);
            uint2 q1 = __ldg(&yb[(size_t)s1 * 32 + lane]);
            uint2 q2 = __ldg(&yb[(size_t)s2 * 32 + lane]);
            uint2 q3 = __ldg(&yb[(size_t)s3 * 32 + lane]);
            a0l = __hadd2(a0l, u2bf2(q0.x)); a0h = __hadd2(a0h, u2bf2(q0.y));
            a1l = __hadd2(a1l, u2bf2(q1.x)); a1h = __hadd2(a1h, u2bf2(q1.y));
            a2l = __hadd2(a2l, u2bf2(q2.x)); a2h = __hadd2(a2h, u2bf2(q2.y));
            a3l = __hadd2(a3l, u2bf2(q3.x)); a3h = __hadd2(a3h, u2bf2(q3.y));
            j += 4;
        }
        for (; j < cnt; j++) {
            int s0 = __shfl_sync(0xffffffffu, idx, j);
            uint2 q0 = __ldg(&yb[(size_t)s0 * 32 + lane]);
            a0l = __hadd2(a0l, u2bf2(q0.x)); a0h = __hadd2(a0h, u2bf2(q0.y));
        }
    }

    float wi = g_inv_in[d];
    float2 f0 = __bfloat1622float2(a0l), f1 = __bfloat1622float2(a1l);
    float2 f2 = __bfloat1622float2(a2l), f3 = __bfloat1622float2(a3l);
    float2 g0 = __bfloat1622float2(a0h), g1 = __bfloat1622float2(a1h);
    float2 g2 = __bfloat1622float2(a2h), g3 = __bfloat1622float2(a3h);
    float ox = (f0.x + f1.x + f2.x + f3.x) * wi;
    float oy = (f0.y + f1.y + f2.y + f3.y) * wi;
    float oz = (g0.x + g1.x + g2.x + g3.x) * wi;
    float ow = (g0.y + g1.y + g2.y + g3.y) * wi;
    __nv_bfloat162 lo = __floats2bfloat162_rn(ox, oy);
    __nv_bfloat162 hi = __floats2bfloat162_rn(oz, ow);
    uint2 pk;
    pk.x = *reinterpret_cast<unsigned*>(&lo);
    pk.y = *reinterpret_cast<unsigned*>(&hi);
    ((uint2*)g_xb)[(size_t)d * 32 + lane] = pk;
}

// ---------------------------------------------------------------------------
// 6) GEMV via tensor cores: y = relu(x @ (W_hi + W_lo) + b), column-summed.
// ---------------------------------------------------------------------------
#define CHUNK 64
#define XSTR 136   // bf16 elements per padded smem row (272B)

__global__ __launch_bounds__(256)
void gemv_mma_kernel(const float* __restrict__ W1, const float* __restrict__ b1,
                     int n_nodes) {
    __shared__ __nv_bfloat16 xs[CHUNK * XSTR];   // 17408 B

    int lane = threadIdx.x & 31;
    int w    = threadIdx.x >> 5;
    int m4   = lane & 3;     // l%4
    int q    = lane >> 2;    // l/4

    unsigned bhi[8][2][2], blo[8][2][2];
#pragma unroll
    for (int kk = 0; kk < 8; kk++) {
#pragma unroll
        for (int t = 0; t < 2; t++) {
            int col = w * 16 + t * 8 + q;
            int k0 = kk * 16 + 2 * m4;
#pragma unroll
            for (int r = 0; r < 2; r++) {
                int ka = k0 + r * 8, kb = ka + 1;
                float wa = W1[ka * DIM + col];
                float wb = W1[kb * DIM + col];
                __nv_bfloat16 ha = __float2bfloat16(wa);
                __nv_bfloat16 hb = __float2bfloat16(wb);
                __nv_bfloat16 la = __float2bfloat16(wa - __bfloat162float(ha));
                __nv_bfloat16 lb = __float2bfloat16(wb - __bfloat162float(hb));
                unsigned ua = *reinterpret_cast<unsigned short*>(&ha);
                unsigned ub = *reinterpret_cast<unsigned short*>(&hb);
                bhi[kk][t][r] = ua | (ub << 16);
                ua = *reinterpret_cast<unsigned short*>(&la);
                ub = *reinterpret_cast<unsigned short*>(&lb);
                blo[kk][t][r] = ua | (ub << 16);
            }
        }
    }

    float be[2], bo[2];
#pragma unroll
    for (int t = 0; t < 2; t++) {
        be[t] = b1[w * 16 + t * 8 + 2 * m4];
        bo[t] = b1[w * 16 + t * 8 + 2 * m4 + 1];
    }

    float cs[2][2];
    cs[0][0] = cs[0][1] = cs[1][0] = cs[1][1] = 0.f;

    const uint2* xg = (const uint2*)g_xb;
    int nchunk = (n_nodes + CHUNK - 1) / CHUNK;

    for (int ch = blockIdx.x; ch < nchunk; ch += gridDim.x) {
        int base = ch * CHUNK;
        __syncthreads();
        for (int i = threadIdx.x; i < CHUNK * 32; i += blockDim.x) {
            int row = i >> 5, c8 = i & 31;
            int n = base + row;
            uint2 v = make_uint2(0u, 0u);
            if (n < n_nodes) v = __ldg(&xg[(size_t)n * 32 + c8]);
            unsigned* dstp = reinterpret_cast<unsigned*>(&xs[row * XSTR + c8 * 4]);
            dstp[0] = v.x; dstp[1] = v.y;
        }
        __syncthreads();

#pragma unroll
        for (int mb = 0; mb < CHUNK / 16; mb++) {
            int rbase = mb * 16;
            float c[2][4];
#pragma unroll
            for (int t = 0; t < 2; t++)
#pragma unroll
                for (int r = 0; r < 4; r++) c[t][r] = 0.f;

#pragma unroll
            for (int kk = 0; kk < 8; kk++) {
                const unsigned* xrow0 = reinterpret_cast<const unsigned*>(
                    &xs[(rbase + q) * XSTR + kk * 16 + 2 * m4]);
                const unsigned* xrow1 = reinterpret_cast<const unsigned*>(
                    &xs[(rbase + q + 8) * XSTR + kk * 16 + 2 * m4]);
                unsigned a0 = xrow0[0];
                unsigned a1 = xrow1[0];
                unsigned a2 = xrow0[4];
                unsigned a3 = xrow1[4];
#pragma unroll
                for (int t = 0; t < 2; t++) {
                    asm volatile(
                        "mma.sync.aligned.m16n8k16.row.col.f32.bf16.bf16.f32 "
                        "{%0,%1,%2,%3}, {%4,%5,%6,%7}, {%8,%9}, {%0,%1,%2,%3};"
                        : "+f"(c[t][0]), "+f"(c[t][1]), "+f"(c[t][2]), "+f"(c[t][3])
                        : "r"(a0), "r"(a1), "r"(a2), "r"(a3),
                          "r"(bhi[kk][t][0]), "r"(bhi[kk][t][1]));
                    asm volatile(
                        "mma.sync.aligned.m16n8k16.row.col.f32.bf16.bf16.f32 "
                        "{%0,%1,%2,%3}, {%4,%5,%6,%7}, {%8,%9}, {%0,%1,%2,%3};"
                        : "+f"(c[t][0]), "+f"(c[t][1]), "+f"(c[t][2]), "+f"(c[t][3])
                        : "r"(a0), "r"(a1), "r"(a2), "r"(a3),
                          "r"(blo[kk][t][0]), "r"(blo[kk][t][1]));
                }
            }

            bool v0 = (base + rbase + q) < n_nodes;
            bool v1 = (base + rbase + q + 8) < n_nodes;
#pragma unroll
            for (int t = 0; t < 2; t++) {
                if (v0) {
                    cs[t][0] += fmaxf(c[t][0] + be[t], 0.f);
                    cs[t][1] += fmaxf(c[t][1] + bo[t], 0.f);
                }
                if (v1) {
                    cs[t][0] += fmaxf(c[t][2] + be[t], 0.f);
                    cs[t][1] += fmaxf(c[t][3] + bo[t], 0.f);
                }
            }
        }
    }

#pragma unroll
    for (int t = 0; t < 2; t++) {
#pragma unroll
        for (int e = 0; e < 2; e++) {
            float v = cs[t][e];
            v += __shfl_xor_sync(0xffffffffu, v, 16);
            v += __shfl_xor_sync(0xffffffffu, v, 8);
            v += __shfl_xor_sync(0xffffffffu, v, 4);
            if (q == 0)
                atomicAdd(&g_z.hsum[w * 16 + t * 8 + 2 * m4 + e], v);
        }
    }
}

// ---------------------------------------------------------------------------
// 7) classifier heads, split-K over 4 warps
// ---------------------------------------------------------------------------
__global__ void head_kernel(const float* __restrict__ Wc1, const float* __restrict__ bc1,
                            const float* __restrict__ Wc2, const float* __restrict__ bc2,
                            float* __restrict__ out, float inv_n) {
    __shared__ float red[128];
    int t = threadIdx.x;
    int o = t & 31;
    int part = t >> 5;
    const float* Wc = (o < 16) ? Wc1 : Wc2;
    int c = o & 15;
    float acc = 0.f;
#pragma unroll 8
    for (int k = part * 32; k < part * 32 + 32; k++)
        acc += g_z.hsum[k] * Wc[k * 16 + c];
    red[t] = acc;
    __syncthreads();
    if (t < 32) {
        const float* bc = (t < 16) ? bc1 : bc2;
        float v = red[t] + red[t + 32] + red[t + 64] + red[t + 96];
        out[t] = v * inv_n + bc[c];
    }
}

// ---------------------------------------------------------------------------
extern "C" void kernel_launch(void* const* d_in, const int* in_sizes, int n_in,
                              void* d_out, int out_size) {
    const float* h   = (const float*)d_in[0];
    const int*   src = (const int*)d_in[1];
    const int*   dst = (const int*)d_in[2];
    const float* W1  = (const float*)d_in[3];
    const float* b1  = (const float*)d_in[4];
    const float* Wc1 = (const float*)d_in[5];
    const float* bc1 = (const float*)d_in[6];
    const float* Wc2 = (const float*)d_in[7];
    const float* bc2 = (const float*)d_in[8];

    int n_nodes = in_sizes[0] / DIM;
    int n_edges = in_sizes[1];
    int n4 = n_edges / 4;

    // One-time side stream + fork/join events (created on the uncaptured
    // correctness call; reused during graph capture — standard pattern).
    static cudaStream_t s1 = nullptr;
    static cudaEvent_t evDeg = nullptr, evPre = nullptr;
    if (s1 == nullptr) {
        cudaStreamCreateWithFlags(&s1, cudaStreamNonBlocking);
        cudaEventCreateWithFlags(&evDeg, cudaEventDisableTiming);
        cudaEventCreateWithFlags(&evPre, cudaEventDisableTiming);
    }

    void* z_p = nullptr;
    cudaGetSymbolAddress(&z_p, g_z);
    cudaMemsetAsync(z_p, 0, sizeof(g_z));

    deg_kernel<<<(n4 + 255) / 256, 256>>>((const int4*)src, (const int4*)dst,
                                          src, dst, n4, n_edges);

    // fork: prescale (needs only deg_out) runs on s1, overlapping scan+fill
    cudaEventRecord(evDeg, 0);
    cudaStreamWaitEvent(s1, evDeg, 0);
    long long nthr = (long long)n_nodes * 32;
    int nblk = (int)((nthr + 255) / 256);
    prescale_kernel<<<nblk, 256, 0, s1>>>((const float4*)h, n_nodes);
    cudaEventRecord(evPre, s1);

    // main chain: scan -> finalize -> fill
    int nb = (n_nodes + SCAN_BLK - 1) / SCAN_BLK;
    scan1_kernel<<<nb, SCAN_BLK>>>(n_nodes);
    scan2_kernel<<<1, 256>>>(nb);
    scan3_kernel<<<(n_nodes + 255) / 256, 256>>>(n_nodes, n_edges);
    fill_kernel<<<(n4 + 255) / 256, 256>>>((const int4*)src, (const int4*)dst,
                                           src, dst, n4, n_edges);

    // join: agg needs yb (s1) + csr/inv_in (main)
    cudaStreamWaitEvent(0, evPre, 0);

    agg_kernel<<<nblk, 256>>>(n_nodes);

    gemv_mma_kernel<<<296, 256>>>(W1, b1, n_nodes);

    head_kernel<<<1, 128>>>(Wc1, bc1, Wc2, bc2, (float*)d_out, 1.0f / (float)n_nodes);
}